// round 7
// baseline (speedup 1.0000x reference)
#include <cuda_runtime.h>

#define BB     4
#define IN_DIM 512
#define HID    1024
#define SEQL   4096
#define RH     64
#define MIDD   12352      /* 2*64*64 + 65*64 */
#define MLPO   24897      /* 2*MIDD + 193 */
#define MLPP   24900      /* padded stride (16B-aligned rows) */

/* ---------------- scratch (no allocation allowed) ---------------- */
__device__ float g_h0[BB * HID];
__device__ float g_z [BB * HID];
__device__ float g_h1[BB * HID];
__device__ float g_h2[BB * HID];
__device__ __align__(16) float g_mlp[BB * MLPP];

/* ---------------- helpers ---------------- */
__device__ __forceinline__ float geluf(float x) {
    return 0.5f * x * (1.0f + erff(x * 0.70710678118654752440f));
}

/* sin with 2-term Cody-Waite 2*pi reduction, then MUFU.SIN.
   Accurate for |x| up to a few thousand (n*lo residual negligible). */
__device__ __forceinline__ float sin_cw(float x) {
    float n = rintf(x * 0.15915494309189535f);       /* 1/(2pi) */
    float r = fmaf(n, -6.2831854820251465f, x);      /* -hi(2pi) */
    r = fmaf(n, 1.7484556e-07f, r);                  /* -lo(2pi) (lo is negative) */
    return __sinf(r);
}

/* ---------------- small GEMM: (4 x KDIM) @ (KDIM x 1024) + bias [, gelu] ----------------
   256 threads: 32 cols x 8 K-slices per block; grid = 32 blocks. */
template<int KDIM, int ACT>
__global__ void __launch_bounds__(256) k_gemm_small(
    const float* __restrict__ A, const float* __restrict__ W,
    const float* __restrict__ bias, float* __restrict__ outv)
{
    __shared__ float As[BB * KDIM];
    __shared__ float red[8][BB][32];
    int tid = threadIdx.x;
    for (int i = tid; i < BB * KDIM; i += 256) As[i] = A[i];
    __syncthreads();

    int col = blockIdx.x * 32 + (tid & 31);
    int sl  = tid >> 5;
    const int KP = KDIM / 8;
    const float* w = W + col;
    float a0 = 0.f, a1 = 0.f, a2 = 0.f, a3 = 0.f;
    int k0 = sl * KP;
    #pragma unroll 8
    for (int k = k0; k < k0 + KP; k++) {
        float wv = __ldg(w + k * HID);
        a0 = fmaf(As[k],            wv, a0);
        a1 = fmaf(As[KDIM + k],     wv, a1);
        a2 = fmaf(As[2 * KDIM + k], wv, a2);
        a3 = fmaf(As[3 * KDIM + k], wv, a3);
    }
    int c = tid & 31;
    red[sl][0][c] = a0; red[sl][1][c] = a1; red[sl][2][c] = a2; red[sl][3][c] = a3;
    __syncthreads();
    if (sl == 0) {
        float s0 = 0.f, s1 = 0.f, s2 = 0.f, s3 = 0.f;
        #pragma unroll
        for (int r = 0; r < 8; r++) {
            s0 += red[r][0][c]; s1 += red[r][1][c];
            s2 += red[r][2][c]; s3 += red[r][3][c];
        }
        float bb = bias[col];
        s0 += bb; s1 += bb; s2 += bb; s3 += bb;
        if (ACT) { s0 = geluf(s0); s1 = geluf(s1); s2 = geluf(s2); s3 = geluf(s3); }
        outv[col]           = s0;
        outv[HID + col]     = s1;
        outv[2 * HID + col] = s2;
        outv[3 * HID + col] = s3;
    }
}

/* ---------------- LayerNorm + gelu over 1024, one block per batch row ------------- */
__global__ void __launch_bounds__(256) k_ln_gelu(
    const float* __restrict__ z, const float* __restrict__ g,
    const float* __restrict__ be, float* __restrict__ outv)
{
    int b = blockIdx.x, tid = threadIdx.x;
    const float* zr = z + b * HID;
    float v0 = zr[tid], v1 = zr[tid + 256], v2 = zr[tid + 512], v3 = zr[tid + 768];
    float s  = v0 + v1 + v2 + v3;
    float s2 = v0 * v0 + v1 * v1 + v2 * v2 + v3 * v3;
    #pragma unroll
    for (int o = 16; o; o >>= 1) {
        s  += __shfl_xor_sync(0xffffffffu, s,  o);
        s2 += __shfl_xor_sync(0xffffffffu, s2, o);
    }
    __shared__ float rs[8], rs2[8], mv[2];
    int w = tid >> 5;
    if ((tid & 31) == 0) { rs[w] = s; rs2[w] = s2; }
    __syncthreads();
    if (tid == 0) {
        float S = 0.f, S2 = 0.f;
        #pragma unroll
        for (int r = 0; r < 8; r++) { S += rs[r]; S2 += rs2[r]; }
        float mu  = S * (1.0f / HID);
        float var = S2 * (1.0f / HID) - mu * mu;
        mv[0] = mu; mv[1] = rsqrtf(var + 1e-5f);
    }
    __syncthreads();
    float mu = mv[0], rr = mv[1];
    float* o = outv + b * HID;
    o[tid]       = geluf(fmaf((v0 - mu) * rr, g[tid],       be[tid]));
    o[tid + 256] = geluf(fmaf((v1 - mu) * rr, g[tid + 256], be[tid + 256]));
    o[tid + 512] = geluf(fmaf((v2 - mu) * rr, g[tid + 512], be[tid + 512]));
    o[tid + 768] = geluf(fmaf((v3 - mu) * rr, g[tid + 768], be[tid + 768]));
}

/* ---------------- big GEMM: (4 x 1024) @ (1024 x 24897) + bias --------------------
   HBM-bound (102 MB of w3). 1 col/thread, 128 threads, deep unroll for MLP.
   Output rows use padded stride MLPP so the ripple kernel can do aligned
   float2 reads from every batch row. */
__global__ void __launch_bounds__(128) k_gemm_big(
    const float* __restrict__ h2, const float* __restrict__ W,
    const float* __restrict__ bias, float* __restrict__ outv)
{
    __shared__ float hs[BB * HID];
    int tid = threadIdx.x;
    for (int i = tid; i < BB * HID; i += 128) hs[i] = h2[i];
    __syncthreads();
    int col = blockIdx.x * 128 + tid;
    if (col >= MLPO) return;
    const float* w = W + col;
    float a0 = 0.f, a1 = 0.f, a2 = 0.f, a3 = 0.f;
    #pragma unroll 16
    for (int k = 0; k < HID; k++) {
        float wv = __ldg(w + k * MLPO);
        a0 = fmaf(hs[k],           wv, a0);
        a1 = fmaf(hs[HID + k],     wv, a1);
        a2 = fmaf(hs[2 * HID + k], wv, a2);
        a3 = fmaf(hs[3 * HID + k], wv, a3);
    }
    float bb = bias[col];
    outv[col]            = a0 + bb;
    outv[MLPP + col]     = a1 + bb;
    outv[2 * MLPP + col] = a2 + bb;
    outv[3 * MLPP + col] = a3 + bb;
}

/* ---------------- ripple network evaluation ---------------------------------------
   Grid (32, 4): blockIdx.y = batch, blockIdx.x = 128-position chunk.
   512 threads = 16 warps; each warp handles 8 positions.
   All middle-layer weights for the batch live in SMEM (padded, conflict-free).
   Per warp i-iteration: 2 float2 + 2 float weight LDS feed 16 sins. */
__global__ void __launch_bounds__(512, 1) k_ripple(
    const float* __restrict__ mlp,
    const float* __restrict__ lcw, const float* __restrict__ lcb,
    const float* __restrict__ bypw, const float* __restrict__ bypb,
    float* __restrict__ outv)
{
    extern __shared__ float sm[];
    float2* wpS   = reinterpret_cast<float2*>(sm);          /* [2][64*65] float2 */
    float*  bwS   = sm + 16640;                              /* [2][64*66]        */
    float*  biasS = sm + 25088;                              /* [2][64]           */
    float2* woS   = reinterpret_cast<float2*>(sm + 25216);   /* [64]              */
    float*  bowS  = sm + 25344;                              /* [64]              */
    float*  lwS   = sm + 25408;
    float*  lbS   = sm + 25472;
    float*  scal  = sm + 25536;                              /* [8]               */
    float*  xsA   = sm + 25544;                              /* [16][512]         */

    int b   = blockIdx.y;
    int tid = threadIdx.x;
    const float* mo = mlp + b * MLPP;   /* MLPP even -> 8B-aligned base */

    /* ---- stage weights (coalesced global reads, <=2-way STS conflicts) ---- */
    #pragma unroll
    for (int L = 0; L < 2; L++) {
        const float* base = mo + L * MIDD;
        const float2* wsrc = reinterpret_cast<const float2*>(base);
        for (int p = tid; p < 4096; p += 512) {
            float2 v = wsrc[p];                 /* (w0,w1) for o=p>>6, i=p&63 */
            wpS[L * 4160 + (p & 63) * 65 + (p >> 6)] = v;
        }
        const float* bsrc = base + 8192;
        for (int k = tid; k < 4160; k += 512) {
            float v = bsrc[k];
            int o = k / 65, j = k - o * 65;
            if (j == 0) biasS[L * 64 + o] = v;
            else        bwS[L * 4224 + (j - 1) * 66 + o] = v;
        }
    }
    if (tid < 64) {
        const float* ob = mo + 2 * MIDD;    /* 8B-aligned: MIDD even */
        woS[tid]  = reinterpret_cast<const float2*>(ob)[tid];
        bowS[tid] = ob[129 + tid];
        lwS[tid]  = lcw[tid];
        lbS[tid]  = lcb[tid];
    }
    if (tid == 0) {
        scal[0] = mo[2 * MIDD + 128];   /* out bias bo0        */
        scal[1] = bypw[0];              /* bypass slope        */
        scal[2] = bypw[1];              /* bypass offset       */
        scal[3] = bypb[0];              /* bypass bias         */
        scal[4] = bypb[1];              /* bypass scale        */
    }
    __syncthreads();

    int warp = tid >> 5, lane = tid & 31;
    float* xs = xsA + warp * 512;                  /* xs[q*64 + i] */
    int pos0 = blockIdx.x * 128 + warp * 8;

    /* ---- initial affine lc_x ---- */
    for (int k = lane; k < 512; k += 32) {
        int q = k >> 6, i = k & 63;
        xs[k] = fmaf((float)(pos0 + q), lwS[i], lbS[i]);
    }
    __syncwarp();

    /* ---- bypass partial (uses original x; 4 lanes per position) ---- */
    float byp;
    {
        float w0v = scal[1], w1v = scal[2];
        const float* xq = xs + (lane >> 2) * 64;
        int i0 = lane & 3;
        float a = 0.f;
        #pragma unroll
        for (int r = 0; r < 16; r++)
            a += sin_cw(fmaf(w0v, xq[i0 + 4 * r], w1v));
        byp = a * scal[4];
    }

    /* ---- two middle ripple layers ---- */
    #pragma unroll
    for (int L = 0; L < 2; L++) {
        const float2* wp = wpS + L * 4160;
        const float*  bw = bwS + L * 4224;
        float accL[8], accH[8];
        #pragma unroll
        for (int q = 0; q < 8; q++) { accL[q] = 0.f; accH[q] = 0.f; }
        #pragma unroll 1
        for (int i = 0; i < 64; i++) {
            float2 wl = wp[i * 65 + lane];
            float2 wh = wp[i * 65 + 32 + lane];
            float  bl = bw[i * 66 + lane];
            float  bh = bw[i * 66 + 32 + lane];
            #pragma unroll
            for (int q = 0; q < 8; q++) {
                float xv = xs[q * 64 + i];
                float al = fmaf(wl.x, xv, wl.y);
                float ah = fmaf(wh.x, xv, wh.y);
                float sl = (L == 0) ? sin_cw(al) : __sinf(al);
                float sh = (L == 0) ? sin_cw(ah) : __sinf(ah);
                accL[q] = fmaf(sl, bl, accL[q]);
                accH[q] = fmaf(sh, bh, accH[q]);
            }
        }
        __syncwarp();
        float cL = biasS[L * 64 + lane], cH = biasS[L * 64 + 32 + lane];
        #pragma unroll
        for (int q = 0; q < 8; q++) {
            xs[q * 64 + lane]      = geluf(accL[q] + cL);
            xs[q * 64 + 32 + lane] = geluf(accH[q] + cH);
        }
        __syncwarp();
    }

    /* ---- output layer (+bypass) with 4-lane split reduction ---- */
    float z = byp;
    {
        const float* xq = xs + (lane >> 2) * 64;
        int i0 = lane & 3;
        #pragma unroll
        for (int r = 0; r < 16; r++) {
            int i = i0 + 4 * r;
            float2 w = woS[i];
            z = fmaf(__sinf(fmaf(w.x, xq[i], w.y)), bowS[i], z);
        }
    }
    z += __shfl_xor_sync(0xffffffffu, z, 1);
    z += __shfl_xor_sync(0xffffffffu, z, 2);
    if ((lane & 3) == 0)
        outv[b * SEQL + pos0 + (lane >> 2)] = z + scal[0] + scal[3];
}

/* ---------------- launch ---------------- */
extern "C" void kernel_launch(void* const* d_in, const int* in_sizes, int n_in,
                              void* d_out, int out_size)
{
    (void)in_sizes; (void)n_in; (void)out_size;
    const float* x   = (const float*)d_in[0];
    const float* w0  = (const float*)d_in[1];
    const float* b0  = (const float*)d_in[2];
    const float* w1  = (const float*)d_in[3];
    const float* b1  = (const float*)d_in[4];
    const float* g1  = (const float*)d_in[5];
    const float* be1 = (const float*)d_in[6];
    const float* w2  = (const float*)d_in[7];
    const float* b2  = (const float*)d_in[8];
    const float* g2  = (const float*)d_in[9];
    const float* be2 = (const float*)d_in[10];
    const float* w3  = (const float*)d_in[11];
    const float* b3  = (const float*)d_in[12];
    const float* lcw = (const float*)d_in[13];
    const float* lcb = (const float*)d_in[14];
    const float* byw = (const float*)d_in[15];
    const float* byb = (const float*)d_in[16];
    float* out = (float*)d_out;

    float *h0, *z, *h1, *h2, *mlp;
    cudaGetSymbolAddress((void**)&h0,  g_h0);
    cudaGetSymbolAddress((void**)&z,   g_z);
    cudaGetSymbolAddress((void**)&h1,  g_h1);
    cudaGetSymbolAddress((void**)&h2,  g_h2);
    cudaGetSymbolAddress((void**)&mlp, g_mlp);

    k_gemm_small<IN_DIM, 1><<<32, 256>>>(x,  w0, b0, h0);
    k_gemm_small<HID,    0><<<32, 256>>>(h0, w1, b1, z);
    k_ln_gelu<<<4, 256>>>(z, g1, be1, h1);
    k_gemm_small<HID,    0><<<32, 256>>>(h1, w2, b2, z);
    k_ln_gelu<<<4, 256>>>(z, g2, be2, h2);
    k_gemm_big<<<(MLPO + 127) / 128, 128>>>(h2, w3, b3, mlp);

    const int rip_smem = 134944;
    cudaFuncSetAttribute(k_ripple, cudaFuncAttributeMaxDynamicSharedMemorySize, rip_smem);
    k_ripple<<<dim3(32, 4), 512, rip_smem>>>(mlp, lcw, lcb, byw, byb, out);
}

// round 8
// speedup vs baseline: 1.3292x; 1.3292x over previous
#include <cuda_runtime.h>

#define BB     4
#define IN_DIM 512
#define HID    1024
#define SEQL   4096
#define RH     64
#define MIDD   12352      /* 2*64*64 + 65*64 */
#define MLPO   24897      /* 2*MIDD + 193 */
#define MLPP   24900      /* padded stride (16B-aligned rows) */
#define KSPLIT 8          /* big-GEMM split-K factor */

/* ---------------- scratch (no allocation allowed) ---------------- */
__device__ float g_h0[BB * HID];
__device__ float g_z [BB * HID];
__device__ float g_h1[BB * HID];
__device__ float g_h2[BB * HID];
__device__ __align__(16) float g_mlp [BB * MLPP];
__device__ __align__(16) float g_part[KSPLIT * BB * MLPP];   /* 3.2 MB partials */

/* ---------------- helpers ---------------- */
__device__ __forceinline__ float geluf(float x) {
    return 0.5f * x * (1.0f + erff(x * 0.70710678118654752440f));
}

/* sin with 2-term Cody-Waite 2*pi reduction, then MUFU.SIN. */
__device__ __forceinline__ float sin_cw(float x) {
    float n = rintf(x * 0.15915494309189535f);
    float r = fmaf(n, -6.2831854820251465f, x);
    r = fmaf(n, 1.7484556e-07f, r);
    return __sinf(r);
}

/* ---------------- small GEMM: (4 x KDIM) @ (KDIM x 1024) + bias [, gelu] ----------
   Block = 256 threads = 8 col-groups(4 cols, float4) x 32 K-slices.
   Grid = 32 blocks (32 cols each). All weight loads are independent float4
   streams -> high MLP, BW-bound instead of latency-bound. */
template<int KDIM, int ACT>
__global__ void __launch_bounds__(256) k_gemm_small(
    const float* __restrict__ A, const float* __restrict__ W,
    const float* __restrict__ bias, float* __restrict__ outv)
{
    __shared__ float As[BB * KDIM];
    __shared__ float red[32 * 132];            /* [slice][128 outputs], padded */
    const int KS = KDIM / 32;                  /* ks per slice */
    int tid = threadIdx.x;
    for (int i = tid; i < BB * KDIM; i += 256) As[i] = A[i];
    __syncthreads();

    int g  = tid & 7;                          /* col-group  */
    int s  = tid >> 3;                         /* k-slice    */
    int col0 = blockIdx.x * 32 + g * 4;
    const float4* w4p = reinterpret_cast<const float4*>(W + col0);

    float acc[4][4];
    #pragma unroll
    for (int b = 0; b < 4; b++)
        #pragma unroll
        for (int j = 0; j < 4; j++) acc[b][j] = 0.f;

    int k0 = s * KS;
    #pragma unroll 8
    for (int k = k0; k < k0 + KS; k++) {
        float4 w = __ldg(w4p + k * (HID / 4));
        #pragma unroll
        for (int b = 0; b < 4; b++) {
            float a = As[b * KDIM + k];
            acc[b][0] = fmaf(a, w.x, acc[b][0]);
            acc[b][1] = fmaf(a, w.y, acc[b][1]);
            acc[b][2] = fmaf(a, w.z, acc[b][2]);
            acc[b][3] = fmaf(a, w.w, acc[b][3]);
        }
    }
    #pragma unroll
    for (int b = 0; b < 4; b++)
        #pragma unroll
        for (int j = 0; j < 4; j++)
            red[s * 132 + g * 16 + b * 4 + j] = acc[b][j];
    __syncthreads();

    if (tid < 128) {                           /* 8 groups x 4 cols x 4 batch */
        float sum = 0.f;
        #pragma unroll
        for (int r = 0; r < 32; r++) sum += red[r * 132 + tid];
        int gg = tid >> 4, c = tid & 15, b = c >> 2, j = c & 3;
        int col = blockIdx.x * 32 + gg * 4 + j;
        sum += bias[col];
        if (ACT) sum = geluf(sum);
        outv[b * HID + col] = sum;
    }
}

/* ---------------- LayerNorm + gelu over 1024, one block per batch row ------------- */
__global__ void __launch_bounds__(256) k_ln_gelu(
    const float* __restrict__ z, const float* __restrict__ g,
    const float* __restrict__ be, float* __restrict__ outv)
{
    int b = blockIdx.x, tid = threadIdx.x;
    const float* zr = z + b * HID;
    float v0 = zr[tid], v1 = zr[tid + 256], v2 = zr[tid + 512], v3 = zr[tid + 768];
    float s  = v0 + v1 + v2 + v3;
    float s2 = v0 * v0 + v1 * v1 + v2 * v2 + v3 * v3;
    #pragma unroll
    for (int o = 16; o; o >>= 1) {
        s  += __shfl_xor_sync(0xffffffffu, s,  o);
        s2 += __shfl_xor_sync(0xffffffffu, s2, o);
    }
    __shared__ float rs[8], rs2[8], mv[2];
    int w = tid >> 5;
    if ((tid & 31) == 0) { rs[w] = s; rs2[w] = s2; }
    __syncthreads();
    if (tid == 0) {
        float S = 0.f, S2 = 0.f;
        #pragma unroll
        for (int r = 0; r < 8; r++) { S += rs[r]; S2 += rs2[r]; }
        float mu  = S * (1.0f / HID);
        float var = S2 * (1.0f / HID) - mu * mu;
        mv[0] = mu; mv[1] = rsqrtf(var + 1e-5f);
    }
    __syncthreads();
    float mu = mv[0], rr = mv[1];
    float* o = outv + b * HID;
    o[tid]       = geluf(fmaf((v0 - mu) * rr, g[tid],       be[tid]));
    o[tid + 256] = geluf(fmaf((v1 - mu) * rr, g[tid + 256], be[tid + 256]));
    o[tid + 512] = geluf(fmaf((v2 - mu) * rr, g[tid + 512], be[tid + 512]));
    o[tid + 768] = geluf(fmaf((v3 - mu) * rr, g[tid + 768], be[tid + 768]));
}

/* ---------------- big GEMM pass 1: split-K x8 partials ----------------------------
   Grid (195, 8) x 128 thr = 200K threads, 128 independent loads each ->
   enough bytes in flight to be HBM-BW bound on the 102 MB w3 stream. */
__global__ void __launch_bounds__(128) k_gemm_big(
    const float* __restrict__ h2, const float* __restrict__ W,
    float* __restrict__ part)
{
    __shared__ float hsp[BB * 128];
    int tid = threadIdx.x;
    int kc  = blockIdx.y;
    int kbase = kc * (HID / KSPLIT);           /* 128 ks per chunk */
    #pragma unroll
    for (int i = 0; i < 4; i++) {
        int idx = tid + i * 128;               /* b = idx>>7, k = idx&127 */
        hsp[idx] = h2[(idx >> 7) * HID + kbase + (idx & 127)];
    }
    __syncthreads();
    int col = blockIdx.x * 128 + tid;
    if (col >= MLPO) return;
    const float* w = W + (size_t)kbase * MLPO + col;
    float a0 = 0.f, a1 = 0.f, a2 = 0.f, a3 = 0.f;
    #pragma unroll 16
    for (int k = 0; k < 128; k++) {
        float wv = __ldg(w + (size_t)k * MLPO);
        a0 = fmaf(hsp[k],       wv, a0);
        a1 = fmaf(hsp[128 + k], wv, a1);
        a2 = fmaf(hsp[256 + k], wv, a2);
        a3 = fmaf(hsp[384 + k], wv, a3);
    }
    float* p = part + (size_t)kc * (BB * MLPP) + col;
    p[0]        = a0;
    p[MLPP]     = a1;
    p[2 * MLPP] = a2;
    p[3 * MLPP] = a3;
}

/* ---------------- big GEMM pass 2: reduce 8 partials + bias ----------------------- */
__global__ void __launch_bounds__(256) k_big_reduce(
    const float* __restrict__ part, const float* __restrict__ bias,
    float* __restrict__ outv)
{
    int idx = blockIdx.x * 256 + threadIdx.x;          /* 4*24897 outputs */
    if (idx >= BB * MLPO) return;
    int b = idx / MLPO, col = idx - b * MLPO;
    const float* p = part + (size_t)b * MLPP + col;
    float s = 0.f;
    #pragma unroll
    for (int kc = 0; kc < KSPLIT; kc++) s += p[(size_t)kc * (BB * MLPP)];
    outv[b * MLPP + col] = s + bias[col];
}

/* ---------------- ripple network evaluation ---------------------------------------
   Grid (37, 4): 148 blocks -> every SM busy. 448 threads = 14 warps x 8 positions
   = 112 positions per block (last block partially active). MUFU-bound. */
__global__ void __launch_bounds__(448, 1) k_ripple(
    const float* __restrict__ mlp,
    const float* __restrict__ lcw, const float* __restrict__ lcb,
    const float* __restrict__ bypw, const float* __restrict__ bypb,
    float* __restrict__ outv)
{
    extern __shared__ float sm[];
    float2* wpS   = reinterpret_cast<float2*>(sm);          /* [2][64*65] float2 */
    float*  bwS   = sm + 16640;                              /* [2][64*66]        */
    float*  biasS = sm + 25088;                              /* [2][64]           */
    float2* woS   = reinterpret_cast<float2*>(sm + 25216);   /* [64]              */
    float*  bowS  = sm + 25344;                              /* [64]              */
    float*  lwS   = sm + 25408;
    float*  lbS   = sm + 25472;
    float*  scal  = sm + 25536;                              /* [8]               */
    float*  xsA   = sm + 25544;                              /* [14][512]         */

    int b   = blockIdx.y;
    int tid = threadIdx.x;
    const float* mo = mlp + b * MLPP;   /* MLPP even -> 8B-aligned base */

    /* ---- stage weights ---- */
    #pragma unroll
    for (int L = 0; L < 2; L++) {
        const float* base = mo + L * MIDD;
        const float2* wsrc = reinterpret_cast<const float2*>(base);
        for (int p = tid; p < 4096; p += 448) {
            float2 v = wsrc[p];                 /* (w0,w1) for o=p>>6, i=p&63 */
            wpS[L * 4160 + (p & 63) * 65 + (p >> 6)] = v;
        }
        const float* bsrc = base + 8192;
        for (int k = tid; k < 4160; k += 448) {
            float v = bsrc[k];
            int o = k / 65, j = k - o * 65;
            if (j == 0) biasS[L * 64 + o] = v;
            else        bwS[L * 4224 + (j - 1) * 66 + o] = v;
        }
    }
    if (tid < 64) {
        const float* ob = mo + 2 * MIDD;
        woS[tid]  = reinterpret_cast<const float2*>(ob)[tid];
        bowS[tid] = ob[129 + tid];
        lwS[tid]  = lcw[tid];
        lbS[tid]  = lcb[tid];
    }
    if (tid == 0) {
        scal[0] = mo[2 * MIDD + 128];   /* out bias bo0  */
        scal[1] = bypw[0];              /* bypass slope  */
        scal[2] = bypw[1];              /* bypass offset */
        scal[3] = bypb[0];              /* bypass bias   */
        scal[4] = bypb[1];              /* bypass scale  */
    }
    __syncthreads();

    int warp = tid >> 5, lane = tid & 31;
    int pos0 = blockIdx.x * 112 + warp * 8;
    if (pos0 >= SEQL) return;
    float* xs = xsA + warp * 512;                  /* xs[q*64 + i] */

    /* ---- initial affine lc_x ---- */
    for (int k = lane; k < 512; k += 32) {
        int q = k >> 6, i = k & 63;
        xs[k] = fmaf((float)(pos0 + q), lwS[i], lbS[i]);
    }
    __syncwarp();

    /* ---- bypass partial (uses original x; 4 lanes per position) ---- */
    float byp;
    {
        float w0v = scal[1], w1v = scal[2];
        const float* xq = xs + (lane >> 2) * 64;
        int i0 = lane & 3;
        float a = 0.f;
        #pragma unroll
        for (int r = 0; r < 16; r++)
            a += sin_cw(fmaf(w0v, xq[i0 + 4 * r], w1v));
        byp = a * scal[4];
    }

    /* ---- two middle ripple layers ---- */
    #pragma unroll
    for (int L = 0; L < 2; L++) {
        const float2* wp = wpS + L * 4160;
        const float*  bw = bwS + L * 4224;
        float accL[8], accH[8];
        #pragma unroll
        for (int q = 0; q < 8; q++) { accL[q] = 0.f; accH[q] = 0.f; }
        #pragma unroll 1
        for (int i = 0; i < 64; i++) {
            float2 wl = wp[i * 65 + lane];
            float2 wh = wp[i * 65 + 32 + lane];
            float  bl = bw[i * 66 + lane];
            float  bh = bw[i * 66 + 32 + lane];
            #pragma unroll
            for (int q = 0; q < 8; q++) {
                float xv = xs[q * 64 + i];
                float al = fmaf(wl.x, xv, wl.y);
                float ah = fmaf(wh.x, xv, wh.y);
                float sl = (L == 0) ? sin_cw(al) : __sinf(al);
                float sh = (L == 0) ? sin_cw(ah) : __sinf(ah);
                accL[q] = fmaf(sl, bl, accL[q]);
                accH[q] = fmaf(sh, bh, accH[q]);
            }
        }
        __syncwarp();
        float cL = biasS[L * 64 + lane], cH = biasS[L * 64 + 32 + lane];
        #pragma unroll
        for (int q = 0; q < 8; q++) {
            xs[q * 64 + lane]      = geluf(accL[q] + cL);
            xs[q * 64 + 32 + lane] = geluf(accH[q] + cH);
        }
        __syncwarp();
    }

    /* ---- output layer (+bypass) with 4-lane split reduction ---- */
    float z = byp;
    {
        const float* xq = xs + (lane >> 2) * 64;
        int i0 = lane & 3;
        #pragma unroll
        for (int r = 0; r < 16; r++) {
            int i = i0 + 4 * r;
            float2 w = woS[i];
            z = fmaf(__sinf(fmaf(w.x, xq[i], w.y)), bowS[i], z);
        }
    }
    z += __shfl_xor_sync(0xffffffffu, z, 1);
    z += __shfl_xor_sync(0xffffffffu, z, 2);
    if ((lane & 3) == 0)
        outv[b * SEQL + pos0 + (lane >> 2)] = z + scal[0] + scal[3];
}

/* ---------------- launch ---------------- */
extern "C" void kernel_launch(void* const* d_in, const int* in_sizes, int n_in,
                              void* d_out, int out_size)
{
    (void)in_sizes; (void)n_in; (void)out_size;
    const float* x   = (const float*)d_in[0];
    const float* w0  = (const float*)d_in[1];
    const float* b0  = (const float*)d_in[2];
    const float* w1  = (const float*)d_in[3];
    const float* b1  = (const float*)d_in[4];
    const float* g1  = (const float*)d_in[5];
    const float* be1 = (const float*)d_in[6];
    const float* w2  = (const float*)d_in[7];
    const float* b2  = (const float*)d_in[8];
    const float* g2  = (const float*)d_in[9];
    const float* be2 = (const float*)d_in[10];
    const float* w3  = (const float*)d_in[11];
    const float* b3  = (const float*)d_in[12];
    const float* lcw = (const float*)d_in[13];
    const float* lcb = (const float*)d_in[14];
    const float* byw = (const float*)d_in[15];
    const float* byb = (const float*)d_in[16];
    float* out = (float*)d_out;

    float *h0, *z, *h1, *h2, *mlp, *part;
    cudaGetSymbolAddress((void**)&h0,   g_h0);
    cudaGetSymbolAddress((void**)&z,    g_z);
    cudaGetSymbolAddress((void**)&h1,   g_h1);
    cudaGetSymbolAddress((void**)&h2,   g_h2);
    cudaGetSymbolAddress((void**)&mlp,  g_mlp);
    cudaGetSymbolAddress((void**)&part, g_part);

    k_gemm_small<IN_DIM, 1><<<32, 256>>>(x,  w0, b0, h0);
    k_gemm_small<HID,    0><<<32, 256>>>(h0, w1, b1, z);
    k_ln_gelu<<<4, 256>>>(z, g1, be1, h1);
    k_gemm_small<HID,    0><<<32, 256>>>(h1, w2, b2, z);
    k_ln_gelu<<<4, 256>>>(z, g2, be2, h2);

    k_gemm_big<<<dim3((MLPO + 127) / 128, KSPLIT), 128>>>(h2, w3, part);
    k_big_reduce<<<(BB * MLPO + 255) / 256, 256>>>(part, b3, mlp);

    const int rip_smem = (25544 + 14 * 512) * 4;   /* 130848 B */
    cudaFuncSetAttribute(k_ripple, cudaFuncAttributeMaxDynamicSharedMemorySize, rip_smem);
    k_ripple<<<dim3(37, 4), 448, rip_smem>>>(mlp, lcw, lcb, byw, byb, out);
}

// round 9
// speedup vs baseline: 2.2298x; 1.6775x over previous
#include <cuda_runtime.h>

#define BB     4
#define IN_DIM 512
#define HID    1024
#define SEQL   4096
#define RH     64
#define MIDD   12352      /* 2*64*64 + 65*64 */
#define MLPO   24897      /* 2*MIDD + 193 */
#define MLPP   24900      /* padded stride (16B-aligned rows) */
#define KSPLIT 8          /* big-GEMM split-K factor */

/* ---------------- scratch (no allocation allowed) ---------------- */
__device__ float g_h1[BB * HID];
__device__ float g_h2[BB * HID];
__device__ __align__(16) float g_pA[8 * BB * HID];           /* small-GEMM partials A */
__device__ __align__(16) float g_pB[8 * BB * HID];           /* small-GEMM partials B */
__device__ __align__(16) float g_mlp [BB * MLPP];
__device__ __align__(16) float g_part[KSPLIT * BB * MLPP];   /* 3.2 MB partials */

/* ---------------- helpers ---------------- */
__device__ __forceinline__ float geluf(float x) {
    return 0.5f * x * (1.0f + erff(x * 0.70710678118654752440f));
}

/* sin with 2-term Cody-Waite 2*pi reduction, then MUFU.SIN. */
__device__ __forceinline__ float sin_cw(float x) {
    float n = rintf(x * 0.15915494309189535f);
    float r = fmaf(n, -6.2831854820251465f, x);
    r = fmaf(n, 1.7484556e-07f, r);
    return __sinf(r);
}

/* ---------------- small GEMM, block-level split-K ---------------------------------
   Grid (16, 8): 16 col-blocks of 64 cols x 8 K-chunks -> 128 blocks (full chip).
   Block 256 thr = 16 col-groups(4 cols, float4) x 16 sub-slices.
   SRCPART=0: A read directly. SRCPART=1: A = gelu(sum of 8 partials + prevb)
   (fused reduction of the previous split-K GEMM). Output: partials. */
template<int KDIM, int SRCPART>
__global__ void __launch_bounds__(256) k_gemm_sk(
    const float* __restrict__ Ain, const float* __restrict__ prevb,
    const float* __restrict__ W, float* __restrict__ part_out)
{
    const int KCH = KDIM / 8;                 /* ks per chunk: 64 or 128 */
    const int KS  = KCH / 16;                 /* ks per sub-slice: 4 or 8 */
    __shared__ float As[BB * KCH];
    __shared__ float red[16 * 256];
    int tid = threadIdx.x;
    int kbase = blockIdx.y * KCH;

    if (SRCPART == 0) {
        for (int i = tid; i < BB * KCH; i += 256) {
            int b = i / KCH, k = i - b * KCH;
            As[i] = Ain[b * KDIM + kbase + k];
        }
    } else {
        for (int i = tid; i < BB * KCH; i += 256) {
            int b = i / KCH, k = i - b * KCH;
            int col = kbase + k;
            float s = 0.f;
            #pragma unroll
            for (int kc = 0; kc < 8; kc++)
                s += Ain[kc * (BB * HID) + b * HID + col];
            As[i] = geluf(s + prevb[col]);
        }
    }
    __syncthreads();

    int g = tid & 15, s = tid >> 4;
    int col0 = blockIdx.x * 64 + g * 4;
    const float4* w4p = reinterpret_cast<const float4*>(W + col0);

    float acc[4][4];
    #pragma unroll
    for (int b = 0; b < 4; b++)
        #pragma unroll
        for (int j = 0; j < 4; j++) acc[b][j] = 0.f;

    int k0 = s * KS;
    #pragma unroll
    for (int k = k0; k < k0 + KS; k++) {
        float4 w = __ldg(w4p + (size_t)(kbase + k) * (HID / 4));
        #pragma unroll
        for (int b = 0; b < 4; b++) {
            float a = As[b * KCH + k];
            acc[b][0] = fmaf(a, w.x, acc[b][0]);
            acc[b][1] = fmaf(a, w.y, acc[b][1]);
            acc[b][2] = fmaf(a, w.z, acc[b][2]);
            acc[b][3] = fmaf(a, w.w, acc[b][3]);
        }
    }
    #pragma unroll
    for (int b = 0; b < 4; b++)
        #pragma unroll
        for (int j = 0; j < 4; j++)
            red[s * 256 + g * 16 + b * 4 + j] = acc[b][j];
    __syncthreads();

    float sum = 0.f;
    #pragma unroll
    for (int r = 0; r < 16; r++) sum += red[r * 256 + tid];
    int gg = tid >> 4, b = (tid >> 2) & 3, j = tid & 3;
    int col = blockIdx.x * 64 + gg * 4 + j;
    part_out[blockIdx.y * (BB * HID) + b * HID + col] = sum;
}

/* ---------------- fused partial-reduce + bias + LayerNorm + gelu ------------------ */
__global__ void __launch_bounds__(256) k_ln_gelu_p(
    const float* __restrict__ part, const float* __restrict__ bias,
    const float* __restrict__ g, const float* __restrict__ be,
    float* __restrict__ outv)
{
    int b = blockIdx.x, tid = threadIdx.x;
    float v[4];
    #pragma unroll
    for (int j = 0; j < 4; j++) {
        int col = tid + j * 256;
        float s = bias[col];
        #pragma unroll
        for (int kc = 0; kc < 8; kc++)
            s += part[kc * (BB * HID) + b * HID + col];
        v[j] = s;
    }
    float s1 = v[0] + v[1] + v[2] + v[3];
    float s2 = v[0]*v[0] + v[1]*v[1] + v[2]*v[2] + v[3]*v[3];
    #pragma unroll
    for (int o = 16; o; o >>= 1) {
        s1 += __shfl_xor_sync(0xffffffffu, s1, o);
        s2 += __shfl_xor_sync(0xffffffffu, s2, o);
    }
    __shared__ float rs[8], rs2[8], mv[2];
    int w = tid >> 5;
    if ((tid & 31) == 0) { rs[w] = s1; rs2[w] = s2; }
    __syncthreads();
    if (tid == 0) {
        float S = 0.f, S2 = 0.f;
        #pragma unroll
        for (int r = 0; r < 8; r++) { S += rs[r]; S2 += rs2[r]; }
        float mu  = S * (1.0f / HID);
        float var = S2 * (1.0f / HID) - mu * mu;
        mv[0] = mu; mv[1] = rsqrtf(var + 1e-5f);
    }
    __syncthreads();
    float mu = mv[0], rr = mv[1];
    float* o = outv + b * HID;
    #pragma unroll
    for (int j = 0; j < 4; j++) {
        int col = tid + j * 256;
        o[col] = geluf(fmaf((v[j] - mu) * rr, g[col], be[col]));
    }
}

/* ---------------- big GEMM pass 1: split-K x8 partials ---------------------------- */
__global__ void __launch_bounds__(128) k_gemm_big(
    const float* __restrict__ h2, const float* __restrict__ W,
    float* __restrict__ part)
{
    __shared__ float hsp[BB * 128];
    int tid = threadIdx.x;
    int kc  = blockIdx.y;
    int kbase = kc * (HID / KSPLIT);           /* 128 ks per chunk */
    #pragma unroll
    for (int i = 0; i < 4; i++) {
        int idx = tid + i * 128;               /* b = idx>>7, k = idx&127 */
        hsp[idx] = h2[(idx >> 7) * HID + kbase + (idx & 127)];
    }
    __syncthreads();
    int col = blockIdx.x * 128 + tid;
    if (col >= MLPO) return;
    const float* w = W + (size_t)kbase * MLPO + col;
    float a0 = 0.f, a1 = 0.f, a2 = 0.f, a3 = 0.f;
    #pragma unroll 16
    for (int k = 0; k < 128; k++) {
        float wv = __ldg(w + (size_t)k * MLPO);
        a0 = fmaf(hsp[k],       wv, a0);
        a1 = fmaf(hsp[128 + k], wv, a1);
        a2 = fmaf(hsp[256 + k], wv, a2);
        a3 = fmaf(hsp[384 + k], wv, a3);
    }
    float* p = part + (size_t)kc * (BB * MLPP) + col;
    p[0]        = a0;
    p[MLPP]     = a1;
    p[2 * MLPP] = a2;
    p[3 * MLPP] = a3;
}

/* ---------------- big GEMM pass 2: reduce 8 partials + bias ----------------------- */
__global__ void __launch_bounds__(256) k_big_reduce(
    const float* __restrict__ part, const float* __restrict__ bias,
    float* __restrict__ outv)
{
    int idx = blockIdx.x * 256 + threadIdx.x;          /* 4*24897 outputs */
    if (idx >= BB * MLPO) return;
    int b = idx / MLPO, col = idx - b * MLPO;
    const float* p = part + (size_t)b * MLPP + col;
    float s = 0.f;
    #pragma unroll
    for (int kc = 0; kc < KSPLIT; kc++) s += p[(size_t)kc * (BB * MLPP)];
    outv[b * MLPP + col] = s + bias[col];
}

/* ---------------- ripple network evaluation ---------------------------------------
   Grid (37, 4): 148 blocks. 448 threads = 14 warps x 8 positions = 112 pos/block. */
__global__ void __launch_bounds__(448, 1) k_ripple(
    const float* __restrict__ mlp,
    const float* __restrict__ lcw, const float* __restrict__ lcb,
    const float* __restrict__ bypw, const float* __restrict__ bypb,
    float* __restrict__ outv)
{
    extern __shared__ float sm[];
    float2* wpS   = reinterpret_cast<float2*>(sm);          /* [2][64*65] float2 */
    float*  bwS   = sm + 16640;                              /* [2][64*66]        */
    float*  biasS = sm + 25088;                              /* [2][64]           */
    float2* woS   = reinterpret_cast<float2*>(sm + 25216);   /* [64]              */
    float*  bowS  = sm + 25344;                              /* [64]              */
    float*  lwS   = sm + 25408;
    float*  lbS   = sm + 25472;
    float*  scal  = sm + 25536;                              /* [8]               */
    float*  xsA   = sm + 25544;                              /* [14][512]         */

    int b   = blockIdx.y;
    int tid = threadIdx.x;
    const float* mo = mlp + b * MLPP;

    #pragma unroll
    for (int L = 0; L < 2; L++) {
        const float* base = mo + L * MIDD;
        const float2* wsrc = reinterpret_cast<const float2*>(base);
        for (int p = tid; p < 4096; p += 448) {
            float2 v = wsrc[p];
            wpS[L * 4160 + (p & 63) * 65 + (p >> 6)] = v;
        }
        const float* bsrc = base + 8192;
        for (int k = tid; k < 4160; k += 448) {
            float v = bsrc[k];
            int o = k / 65, j = k - o * 65;
            if (j == 0) biasS[L * 64 + o] = v;
            else        bwS[L * 4224 + (j - 1) * 66 + o] = v;
        }
    }
    if (tid < 64) {
        const float* ob = mo + 2 * MIDD;
        woS[tid]  = reinterpret_cast<const float2*>(ob)[tid];
        bowS[tid] = ob[129 + tid];
        lwS[tid]  = lcw[tid];
        lbS[tid]  = lcb[tid];
    }
    if (tid == 0) {
        scal[0] = mo[2 * MIDD + 128];
        scal[1] = bypw[0];
        scal[2] = bypw[1];
        scal[3] = bypb[0];
        scal[4] = bypb[1];
    }
    __syncthreads();

    int warp = tid >> 5, lane = tid & 31;
    int pos0 = blockIdx.x * 112 + warp * 8;
    if (pos0 >= SEQL) return;
    float* xs = xsA + warp * 512;

    for (int k = lane; k < 512; k += 32) {
        int q = k >> 6, i = k & 63;
        xs[k] = fmaf((float)(pos0 + q), lwS[i], lbS[i]);
    }
    __syncwarp();

    float byp;
    {
        float w0v = scal[1], w1v = scal[2];
        const float* xq = xs + (lane >> 2) * 64;
        int i0 = lane & 3;
        float a = 0.f;
        #pragma unroll
        for (int r = 0; r < 16; r++)
            a += sin_cw(fmaf(w0v, xq[i0 + 4 * r], w1v));
        byp = a * scal[4];
    }

    #pragma unroll
    for (int L = 0; L < 2; L++) {
        const float2* wp = wpS + L * 4160;
        const float*  bw = bwS + L * 4224;
        float accL[8], accH[8];
        #pragma unroll
        for (int q = 0; q < 8; q++) { accL[q] = 0.f; accH[q] = 0.f; }
        #pragma unroll 1
        for (int i = 0; i < 64; i++) {
            float2 wl = wp[i * 65 + lane];
            float2 wh = wp[i * 65 + 32 + lane];
            float  bl = bw[i * 66 + lane];
            float  bh = bw[i * 66 + 32 + lane];
            #pragma unroll
            for (int q = 0; q < 8; q++) {
                float xv = xs[q * 64 + i];
                float al = fmaf(wl.x, xv, wl.y);
                float ah = fmaf(wh.x, xv, wh.y);
                float sl = (L == 0) ? sin_cw(al) : __sinf(al);
                float sh = (L == 0) ? sin_cw(ah) : __sinf(ah);
                accL[q] = fmaf(sl, bl, accL[q]);
                accH[q] = fmaf(sh, bh, accH[q]);
            }
        }
        __syncwarp();
        float cL = biasS[L * 64 + lane], cH = biasS[L * 64 + 32 + lane];
        #pragma unroll
        for (int q = 0; q < 8; q++) {
            xs[q * 64 + lane]      = geluf(accL[q] + cL);
            xs[q * 64 + 32 + lane] = geluf(accH[q] + cH);
        }
        __syncwarp();
    }

    float z = byp;
    {
        const float* xq = xs + (lane >> 2) * 64;
        int i0 = lane & 3;
        #pragma unroll
        for (int r = 0; r < 16; r++) {
            int i = i0 + 4 * r;
            float2 w = woS[i];
            z = fmaf(__sinf(fmaf(w.x, xq[i], w.y)), bowS[i], z);
        }
    }
    z += __shfl_xor_sync(0xffffffffu, z, 1);
    z += __shfl_xor_sync(0xffffffffu, z, 2);
    if ((lane & 3) == 0)
        outv[b * SEQL + pos0 + (lane >> 2)] = z + scal[0] + scal[3];
}

/* ---------------- launch ---------------- */
extern "C" void kernel_launch(void* const* d_in, const int* in_sizes, int n_in,
                              void* d_out, int out_size)
{
    (void)in_sizes; (void)n_in; (void)out_size;
    const float* x   = (const float*)d_in[0];
    const float* w0  = (const float*)d_in[1];
    const float* b0  = (const float*)d_in[2];
    const float* w1  = (const float*)d_in[3];
    const float* b1  = (const float*)d_in[4];
    const float* g1  = (const float*)d_in[5];
    const float* be1 = (const float*)d_in[6];
    const float* w2  = (const float*)d_in[7];
    const float* b2  = (const float*)d_in[8];
    const float* g2  = (const float*)d_in[9];
    const float* be2 = (const float*)d_in[10];
    const float* w3  = (const float*)d_in[11];
    const float* b3  = (const float*)d_in[12];
    const float* lcw = (const float*)d_in[13];
    const float* lcb = (const float*)d_in[14];
    const float* byw = (const float*)d_in[15];
    const float* byb = (const float*)d_in[16];
    float* out = (float*)d_out;

    float *h1, *h2, *pA, *pB, *mlp, *part;
    cudaGetSymbolAddress((void**)&h1,   g_h1);
    cudaGetSymbolAddress((void**)&h2,   g_h2);
    cudaGetSymbolAddress((void**)&pA,   g_pA);
    cudaGetSymbolAddress((void**)&pB,   g_pB);
    cudaGetSymbolAddress((void**)&mlp,  g_mlp);
    cudaGetSymbolAddress((void**)&part, g_part);

    /* h0 = gelu(x@w0+b0) kept as partials pA; fused into next stage */
    k_gemm_sk<IN_DIM, 0><<<dim3(16, 8), 256>>>(x,  nullptr, w0, pA);
    /* z1 = gelu-reduced(pA,b0) @ w1 -> partials pB */
    k_gemm_sk<HID,    1><<<dim3(16, 8), 256>>>(pA, b0, w1, pB);
    /* h1 = gelu(LN(reduce(pB)+b1)) */
    k_ln_gelu_p<<<4, 256>>>(pB, b1, g1, be1, h1);
    /* z2 = h1 @ w2 -> partials pA */
    k_gemm_sk<HID,    0><<<dim3(16, 8), 256>>>(h1, nullptr, w2, pA);
    /* h2 = gelu(LN(reduce(pA)+b2)) */
    k_ln_gelu_p<<<4, 256>>>(pA, b2, g2, be2, h2);

    k_gemm_big<<<dim3((MLPO + 127) / 128, KSPLIT), 128>>>(h2, w3, part);
    k_big_reduce<<<(BB * MLPO + 255) / 256, 256>>>(part, b3, mlp);

    const int rip_smem = (25544 + 14 * 512) * 4;   /* 130848 B */
    cudaFuncSetAttribute(k_ripple, cudaFuncAttributeMaxDynamicSharedMemorySize, rip_smem);
    k_ripple<<<dim3(37, 4), 448, rip_smem>>>(mlp, lcw, lcb, byw, byb, out);
}

// round 11
// speedup vs baseline: 2.2838x; 1.0242x over previous
#include <cuda_runtime.h>

#define BB     4
#define IN_DIM 512
#define HID    1024
#define SEQL   4096
#define RH     64
#define MIDD   12352      /* 2*64*64 + 65*64 */
#define MLPO   24897      /* 2*MIDD + 193 */
#define MLPP   24900      /* padded stride (16B-aligned rows) */
#define KSPLIT 8          /* big-GEMM split-K factor */

/* ---------------- scratch (no allocation allowed) ---------------- */
__device__ float g_h1[BB * HID];
__device__ float g_h2[BB * HID];
__device__ __align__(16) float g_pA[8 * BB * HID];           /* small-GEMM partials A */
__device__ __align__(16) float g_pB[8 * BB * HID];           /* small-GEMM partials B */
__device__ __align__(16) float g_mlp [BB * MLPP];
__device__ __align__(16) float g_part[KSPLIT * BB * MLPP];   /* 3.2 MB partials */

/* ---------------- helpers ---------------- */
__device__ __forceinline__ float geluf(float x) {
    return 0.5f * x * (1.0f + erff(x * 0.70710678118654752440f));
}

/* 2-term Cody-Waite 2*pi reduction (bypass path, tight accuracy). */
__device__ __forceinline__ float sin_cw(float x) {
    float n = rintf(x * 0.15915494309189535f);
    float r = fmaf(n, -6.2831854820251465f, x);
    r = fmaf(n, 1.7484556e-07f, r);
    return __sinf(r);
}

/* 1-term reduction: angle err 1.75e-7*n (n<~400 here) -> ~5e-5 abs, fine vs 1e-3. */
__device__ __forceinline__ float sin_cw1(float x) {
    float n = rintf(x * 0.15915494309189535f);
    return __sinf(fmaf(n, -6.2831854820251465f, x));
}

/* ---------------- small GEMM, block-level split-K ---------------------------------
   Grid (16, 8): 16 col-blocks of 64 cols x 8 K-chunks. Block 256 thr =
   16 col-groups(4 cols, float4) x 16 sub-slices. Weight loads are issued
   FIRST into a register buffer (front-batched, MLP=KS) so the full 4 MB
   matrix is in flight in one latency window; As staging hides underneath.
   SRCPART=1: A = gelu(sum of 8 partials + prevb) fused. Output: partials. */
template<int KDIM, int SRCPART>
__global__ void __launch_bounds__(256) k_gemm_sk(
    const float* __restrict__ Ain, const float* __restrict__ prevb,
    const float* __restrict__ W, float* __restrict__ part_out)
{
    const int KCH = KDIM / 8;                 /* ks per chunk: 64 or 128 */
    const int KS  = KCH / 16;                 /* ks per sub-slice: 4 or 8 */
    __shared__ float As[BB * KCH];
    __shared__ float red[16 * 256];
    int tid = threadIdx.x;
    int kbase = blockIdx.y * KCH;
    int g = tid & 15, s = tid >> 4;
    int col0 = blockIdx.x * 64 + g * 4;
    const float4* w4p = reinterpret_cast<const float4*>(W + col0);
    int k0 = s * KS;

    /* phase 1: issue ALL weight loads (independent, front-batched) */
    float4 wbuf[KS];
    #pragma unroll
    for (int k = 0; k < KS; k++)
        wbuf[k] = __ldg(w4p + (size_t)(kbase + k0 + k) * (HID / 4));

    /* phase 2: stage A (overlaps with weight-load latency) */
    if (SRCPART == 0) {
        for (int i = tid; i < BB * KCH; i += 256) {
            int b = i / KCH, k = i - b * KCH;
            As[i] = Ain[b * KDIM + kbase + k];
        }
    } else {
        for (int i = tid; i < BB * KCH; i += 256) {
            int b = i / KCH, k = i - b * KCH;
            int col = kbase + k;
            float ss = 0.f;
            #pragma unroll
            for (int kc = 0; kc < 8; kc++)
                ss += Ain[kc * (BB * HID) + b * HID + col];
            As[i] = geluf(ss + prevb[col]);
        }
    }
    __syncthreads();

    /* phase 3: FMA from registers */
    float acc[4][4];
    #pragma unroll
    for (int b = 0; b < 4; b++)
        #pragma unroll
        for (int j = 0; j < 4; j++) acc[b][j] = 0.f;

    #pragma unroll
    for (int k = 0; k < KS; k++) {
        float4 w = wbuf[k];
        #pragma unroll
        for (int b = 0; b < 4; b++) {
            float a = As[b * KCH + k0 + k];
            acc[b][0] = fmaf(a, w.x, acc[b][0]);
            acc[b][1] = fmaf(a, w.y, acc[b][1]);
            acc[b][2] = fmaf(a, w.z, acc[b][2]);
            acc[b][3] = fmaf(a, w.w, acc[b][3]);
        }
    }
    #pragma unroll
    for (int b = 0; b < 4; b++)
        #pragma unroll
        for (int j = 0; j < 4; j++)
            red[s * 256 + g * 16 + b * 4 + j] = acc[b][j];
    __syncthreads();

    float sum = 0.f;
    #pragma unroll
    for (int r = 0; r < 16; r++) sum += red[r * 256 + tid];
    int gg = tid >> 4, b = (tid >> 2) & 3, j = tid & 3;
    int col = blockIdx.x * 64 + gg * 4 + j;
    part_out[blockIdx.y * (BB * HID) + b * HID + col] = sum;
}

/* ---------------- fused partial-reduce + bias + LayerNorm + gelu ------------------ */
__global__ void __launch_bounds__(256) k_ln_gelu_p(
    const float* __restrict__ part, const float* __restrict__ bias,
    const float* __restrict__ g, const float* __restrict__ be,
    float* __restrict__ outv)
{
    int b = blockIdx.x, tid = threadIdx.x;
    float v[4];
    #pragma unroll
    for (int j = 0; j < 4; j++) {
        int col = tid + j * 256;
        float s = bias[col];
        #pragma unroll
        for (int kc = 0; kc < 8; kc++)
            s += part[kc * (BB * HID) + b * HID + col];
        v[j] = s;
    }
    float s1 = v[0] + v[1] + v[2] + v[3];
    float s2 = v[0]*v[0] + v[1]*v[1] + v[2]*v[2] + v[3]*v[3];
    #pragma unroll
    for (int o = 16; o; o >>= 1) {
        s1 += __shfl_xor_sync(0xffffffffu, s1, o);
        s2 += __shfl_xor_sync(0xffffffffu, s2, o);
    }
    __shared__ float rs[8], rs2[8], mv[2];
    int w = tid >> 5;
    if ((tid & 31) == 0) { rs[w] = s1; rs2[w] = s2; }
    __syncthreads();
    if (tid == 0) {
        float S = 0.f, S2 = 0.f;
        #pragma unroll
        for (int r = 0; r < 8; r++) { S += rs[r]; S2 += rs2[r]; }
        float mu  = S * (1.0f / HID);
        float var = S2 * (1.0f / HID) - mu * mu;
        mv[0] = mu; mv[1] = rsqrtf(var + 1e-5f);
    }
    __syncthreads();
    float mu = mv[0], rr = mv[1];
    float* o = outv + b * HID;
    #pragma unroll
    for (int j = 0; j < 4; j++) {
        int col = tid + j * 256;
        o[col] = geluf(fmaf((v[j] - mu) * rr, g[col], be[col]));
    }
}

/* ---------------- big GEMM pass 1: split-K x8 partials ---------------------------- */
__global__ void __launch_bounds__(128) k_gemm_big(
    const float* __restrict__ h2, const float* __restrict__ W,
    float* __restrict__ part)
{
    __shared__ float hsp[BB * 128];
    int tid = threadIdx.x;
    int kc  = blockIdx.y;
    int kbase = kc * (HID / KSPLIT);           /* 128 ks per chunk */
    #pragma unroll
    for (int i = 0; i < 4; i++) {
        int idx = tid + i * 128;               /* b = idx>>7, k = idx&127 */
        hsp[idx] = h2[(idx >> 7) * HID + kbase + (idx & 127)];
    }
    __syncthreads();
    int col = blockIdx.x * 128 + tid;
    if (col >= MLPO) return;
    const float* w = W + (size_t)kbase * MLPO + col;
    float a0 = 0.f, a1 = 0.f, a2 = 0.f, a3 = 0.f;
    #pragma unroll 16
    for (int k = 0; k < 128; k++) {
        float wv = __ldg(w + (size_t)k * MLPO);
        a0 = fmaf(hsp[k],       wv, a0);
        a1 = fmaf(hsp[128 + k], wv, a1);
        a2 = fmaf(hsp[256 + k], wv, a2);
        a3 = fmaf(hsp[384 + k], wv, a3);
    }
    float* p = part + (size_t)kc * (BB * MLPP) + col;
    p[0]        = a0;
    p[MLPP]     = a1;
    p[2 * MLPP] = a2;
    p[3 * MLPP] = a3;
}

/* ---------------- big GEMM pass 2: float4 reduce over padded domain --------------- */
__global__ void __launch_bounds__(256) k_big_reduce(
    const float* __restrict__ part, const float* __restrict__ bias,
    float* __restrict__ outv)
{
    int idx = blockIdx.x * 256 + threadIdx.x;          /* BB*MLPP/4 vec4 outputs */
    if (idx >= BB * (MLPP / 4)) return;
    int b = idx / (MLPP / 4), v = idx - b * (MLPP / 4);
    const float4* p = reinterpret_cast<const float4*>(part + (size_t)b * MLPP) + v;
    float4 s = {0.f, 0.f, 0.f, 0.f};
    #pragma unroll
    for (int kc = 0; kc < KSPLIT; kc++) {
        float4 t = p[(size_t)kc * (BB * MLPP / 4)];
        s.x += t.x; s.y += t.y; s.z += t.z; s.w += t.w;
    }
    int col = v * 4;
    s.x += (col     < MLPO) ? bias[col]     : 0.f;
    s.y += (col + 1 < MLPO) ? bias[col + 1] : 0.f;
    s.z += (col + 2 < MLPO) ? bias[col + 2] : 0.f;
    s.w += (col + 3 < MLPO) ? bias[col + 3] : 0.f;
    reinterpret_cast<float4*>(outv + (size_t)b * MLPP)[v] = s;
}

/* ---------------- ripple network evaluation ---------------------------------------
   Grid (37, 4): 148 blocks. 448 threads = 14 warps x 8 positions = 112 pos/block. */
__global__ void __launch_bounds__(448, 1) k_ripple(
    const float* __restrict__ mlp,
    const float* __restrict__ lcw, const float* __restrict__ lcb,
    const float* __restrict__ bypw, const float* __restrict__ bypb,
    float* __restrict__ outv)
{
    extern __shared__ float sm[];
    float2* wpS   = reinterpret_cast<float2*>(sm);          /* [2][64*65] float2 */
    float*  bwS   = sm + 16640;                              /* [2][64*66]        */
    float*  biasS = sm + 25088;                              /* [2][64]           */
    float2* woS   = reinterpret_cast<float2*>(sm + 25216);   /* [64]              */
    float*  bowS  = sm + 25344;                              /* [64]              */
    float*  lwS   = sm + 25408;
    float*  lbS   = sm + 25472;
    float*  scal  = sm + 25536;                              /* [8]               */
    float*  xsA   = sm + 25544;                              /* [14][512]         */

    int b   = blockIdx.y;
    int tid = threadIdx.x;
    const float* mo = mlp + b * MLPP;

    #pragma unroll
    for (int L = 0; L < 2; L++) {
        const float* base = mo + L * MIDD;
        const float2* wsrc = reinterpret_cast<const float2*>(base);
        for (int p = tid; p < 4096; p += 448) {
            float2 v = wsrc[p];
            wpS[L * 4160 + (p & 63) * 65 + (p >> 6)] = v;
        }
        const float* bsrc = base + 8192;
        for (int k = tid; k < 4160; k += 448) {
            float v = bsrc[k];
            int o = k / 65, j = k - o * 65;
            if (j == 0) biasS[L * 64 + o] = v;
            else        bwS[L * 4224 + (j - 1) * 66 + o] = v;
        }
    }
    if (tid < 64) {
        const float* ob = mo + 2 * MIDD;
        woS[tid]  = reinterpret_cast<const float2*>(ob)[tid];
        bowS[tid] = ob[129 + tid];
        lwS[tid]  = lcw[tid];
        lbS[tid]  = lcb[tid];
    }
    if (tid == 0) {
        scal[0] = mo[2 * MIDD + 128];
        scal[1] = bypw[0];
        scal[2] = bypw[1];
        scal[3] = bypb[0];
        scal[4] = bypb[1];
    }
    __syncthreads();

    int warp = tid >> 5, lane = tid & 31;
    int pos0 = blockIdx.x * 112 + warp * 8;
    if (pos0 >= SEQL) return;
    float* xs = xsA + warp * 512;

    for (int k = lane; k < 512; k += 32) {
        int q = k >> 6, i = k & 63;
        xs[k] = fmaf((float)(pos0 + q), lwS[i], lbS[i]);
    }
    __syncwarp();

    float byp;
    {
        float w0v = scal[1], w1v = scal[2];
        const float* xq = xs + (lane >> 2) * 64;
        int i0 = lane & 3;
        float a = 0.f;
        #pragma unroll
        for (int r = 0; r < 16; r++)
            a += sin_cw(fmaf(w0v, xq[i0 + 4 * r], w1v));
        byp = a * scal[4];
    }

    #pragma unroll
    for (int L = 0; L < 2; L++) {
        const float2* wp = wpS + L * 4160;
        const float*  bw = bwS + L * 4224;
        float accL[8], accH[8];
        #pragma unroll
        for (int q = 0; q < 8; q++) { accL[q] = 0.f; accH[q] = 0.f; }
        #pragma unroll 1
        for (int i = 0; i < 64; i++) {
            float2 wl = wp[i * 65 + lane];
            float2 wh = wp[i * 65 + 32 + lane];
            float  bl = bw[i * 66 + lane];
            float  bh = bw[i * 66 + 32 + lane];
            #pragma unroll
            for (int q = 0; q < 8; q++) {
                float xv = xs[q * 64 + i];
                float al = fmaf(wl.x, xv, wl.y);
                float ah = fmaf(wh.x, xv, wh.y);
                float sl = (L == 0) ? sin_cw1(al) : __sinf(al);
                float sh = (L == 0) ? sin_cw1(ah) : __sinf(ah);
                accL[q] = fmaf(sl, bl, accL[q]);
                accH[q] = fmaf(sh, bh, accH[q]);
            }
        }
        __syncwarp();
        float cL = biasS[L * 64 + lane], cH = biasS[L * 64 + 32 + lane];
        #pragma unroll
        for (int q = 0; q < 8; q++) {
            xs[q * 64 + lane]      = geluf(accL[q] + cL);
            xs[q * 64 + 32 + lane] = geluf(accH[q] + cH);
        }
        __syncwarp();
    }

    float z = byp;
    {
        const float* xq = xs + (lane >> 2) * 64;
        int i0 = lane & 3;
        #pragma unroll
        for (int r = 0; r < 16; r++) {
            int i = i0 + 4 * r;
            float2 w = woS[i];
            z = fmaf(__sinf(fmaf(w.x, xq[i], w.y)), bowS[i], z);
        }
    }
    z += __shfl_xor_sync(0xffffffffu, z, 1);
    z += __shfl_xor_sync(0xffffffffu, z, 2);
    if ((lane & 3) == 0)
        outv[b * SEQL + pos0 + (lane >> 2)] = z + scal[0] + scal[3];
}

/* ---------------- launch ---------------- */
extern "C" void kernel_launch(void* const* d_in, const int* in_sizes, int n_in,
                              void* d_out, int out_size)
{
    (void)in_sizes; (void)n_in; (void)out_size;
    const float* x   = (const float*)d_in[0];
    const float* w0  = (const float*)d_in[1];
    const float* b0  = (const float*)d_in[2];
    const float* w1  = (const float*)d_in[3];
    const float* b1  = (const float*)d_in[4];
    const float* g1  = (const float*)d_in[5];
    const float* be1 = (const float*)d_in[6];
    const float* w2  = (const float*)d_in[7];
    const float* b2  = (const float*)d_in[8];
    const float* g2  = (const float*)d_in[9];
    const float* be2 = (const float*)d_in[10];
    const float* w3  = (const float*)d_in[11];
    const float* b3  = (const float*)d_in[12];
    const float* lcw = (const float*)d_in[13];
    const float* lcb = (const float*)d_in[14];
    const float* byw = (const float*)d_in[15];
    const float* byb = (const float*)d_in[16];
    float* out = (float*)d_out;

    float *h1, *h2, *pA, *pB, *mlp, *part;
    cudaGetSymbolAddress((void**)&h1,   g_h1);
    cudaGetSymbolAddress((void**)&h2,   g_h2);
    cudaGetSymbolAddress((void**)&pA,   g_pA);
    cudaGetSymbolAddress((void**)&pB,   g_pB);
    cudaGetSymbolAddress((void**)&mlp,  g_mlp);
    cudaGetSymbolAddress((void**)&part, g_part);

    k_gemm_sk<IN_DIM, 0><<<dim3(16, 8), 256>>>(x,  nullptr, w0, pA);
    k_gemm_sk<HID,    1><<<dim3(16, 8), 256>>>(pA, b0, w1, pB);
    k_ln_gelu_p<<<4, 256>>>(pB, b1, g1, be1, h1);
    k_gemm_sk<HID,    0><<<dim3(16, 8), 256>>>(h1, nullptr, w2, pA);
    k_ln_gelu_p<<<4, 256>>>(pA, b2, g2, be2, h2);

    k_gemm_big<<<dim3((MLPO + 127) / 128, KSPLIT), 128>>>(h2, w3, part);
    k_big_reduce<<<(BB * (MLPP / 4) + 255) / 256, 256>>>(part, b3, mlp);

    const int rip_smem = (25544 + 14 * 512) * 4;   /* 130848 B */
    cudaFuncSetAttribute(k_ripple, cudaFuncAttributeMaxDynamicSharedMemorySize, rip_smem);
    k_ripple<<<dim3(37, 4), 448, rip_smem>>>(mlp, lcw, lcb, byw, byb, out);
}

// round 14
// speedup vs baseline: 2.6969x; 1.1809x over previous
#include <cuda_runtime.h>

#define BB     4
#define IN_DIM 512
#define HID    1024
#define SEQL   4096
#define RH     64
#define MIDD   12352      /* 2*64*64 + 65*64 */
#define MLPO   24897      /* 2*MIDD + 193 */
#define MLPP   24900      /* padded stride (16B-aligned rows) */
#define KSPLIT 8          /* split-K factor (small + big GEMMs) */

/* ---------------- scratch (no allocation allowed) ---------------- */
__device__ float g_h2[BB * HID];
__device__ __align__(16) float g_pA[KSPLIT * BB * HID];
__device__ __align__(16) float g_pB[KSPLIT * BB * HID];
__device__ __align__(16) float g_mlp [BB * MLPP];
__device__ __align__(16) float g_part[KSPLIT * BB * MLPP];

/* ---------------- helpers ---------------- */
__device__ __forceinline__ float geluf(float x) {
    return 0.5f * x * (1.0f + erff(x * 0.70710678118654752440f));
}

/* 2-term Cody-Waite 2*pi reduction (bypass path: args up to ~4000). */
__device__ __forceinline__ float sin_cw(float x) {
    float n = rintf(x * 0.15915494309189535f);
    float r = fmaf(n, -6.2831854820251465f, x);
    r = fmaf(n, 1.7484556e-07f, r);
    return __sinf(r);
}

/* ---------------- small GEMM, block-level split-K ---------------------------------
   Grid (32, 8): 32 col-blocks of 32 cols x 8 K-chunks = 256 blocks (~1.7/SM).
   Block 256 thr = 8 col-groups(4 cols, float4) x 32 K-sub-slices; weight loads
   front-batched into registers (KS independent float4 per thread).
   SRCPART=0: A direct.  SRCPART=1: A = gelu(sum8 partials + prevb).
   SRCPART=2: A = gelu(LN(sum8 partials + prevb)) — LN stats computed
   block-locally from the L2-resident partial buffer.  Output: partials. */
template<int KDIM, int SRCPART>
__global__ void __launch_bounds__(256) k_gemm_sk(
    const float* __restrict__ Ain, const float* __restrict__ prevb,
    const float* __restrict__ lng, const float* __restrict__ lnb,
    const float* __restrict__ W, float* __restrict__ part_out)
{
    const int KCH = KDIM / 8;                 /* 64 or 128 */
    const int KS  = KCH / 32;                 /* 2 or 4    */
    __shared__ float As[BB * KCH];
    __shared__ float red[32 * 128];
    int tid = threadIdx.x;
    int kbase = blockIdx.y * KCH;
    int g = tid & 7, s = tid >> 3;
    int col0 = blockIdx.x * 32 + g * 4;
    const float4* w4p = reinterpret_cast<const float4*>(W + col0);
    int k0 = s * KS;

    /* phase 1: issue ALL weight loads (independent, front-batched) */
    float4 wbuf[KS];
    #pragma unroll
    for (int k = 0; k < KS; k++)
        wbuf[k] = __ldg(w4p + (size_t)(kbase + k0 + k) * (HID / 4));

    /* phase 2: stage A (overlaps weight-load latency) */
    if (SRCPART == 0) {
        for (int i = tid; i < BB * KCH; i += 256) {
            int b = i / KCH, k = i - b * KCH;
            As[i] = Ain[b * KDIM + kbase + k];
        }
    } else if (SRCPART == 1) {
        for (int i = tid; i < BB * KCH; i += 256) {
            int b = i / KCH, k = i - b * KCH;
            int col = kbase + k;
            float ss = 0.f;
            #pragma unroll
            for (int kc = 0; kc < KSPLIT; kc++)
                ss += Ain[kc * (BB * HID) + b * HID + col];
            As[i] = geluf(ss + prevb[col]);
        }
    } else {
        /* fused reduce + bias + LayerNorm + gelu */
        __shared__ float vS[BB * HID];               /* 16 KB */
        __shared__ float wred[8][BB][2];
        __shared__ float stat[BB][2];
        float ps1[BB], ps2[BB];
        #pragma unroll
        for (int b = 0; b < BB; b++) { ps1[b] = 0.f; ps2[b] = 0.f; }
        #pragma unroll
        for (int b = 0; b < BB; b++) {
            #pragma unroll
            for (int j = 0; j < 4; j++) {
                int col = tid + j * 256;
                float ss = prevb[col];
                #pragma unroll
                for (int kc = 0; kc < KSPLIT; kc++)
                    ss += Ain[kc * (BB * HID) + b * HID + col];
                vS[b * HID + col] = ss;
                ps1[b] += ss;
                ps2[b] += ss * ss;
            }
        }
        #pragma unroll
        for (int b = 0; b < BB; b++) {
            float s1 = ps1[b], s2 = ps2[b];
            #pragma unroll
            for (int o = 16; o; o >>= 1) {
                s1 += __shfl_xor_sync(0xffffffffu, s1, o);
                s2 += __shfl_xor_sync(0xffffffffu, s2, o);
            }
            if ((tid & 31) == 0) { wred[tid >> 5][b][0] = s1; wred[tid >> 5][b][1] = s2; }
        }
        __syncthreads();
        if (tid < BB) {
            float S = 0.f, S2 = 0.f;
            #pragma unroll
            for (int r = 0; r < 8; r++) { S += wred[r][tid][0]; S2 += wred[r][tid][1]; }
            float mu  = S * (1.0f / HID);
            float var = S2 * (1.0f / HID) - mu * mu;
            stat[tid][0] = mu; stat[tid][1] = rsqrtf(var + 1e-5f);
        }
        __syncthreads();
        for (int i = tid; i < BB * KCH; i += 256) {
            int b = i / KCH, k = i - b * KCH;
            int col = kbase + k;
            float v = (vS[b * HID + col] - stat[b][0]) * stat[b][1];
            As[i] = geluf(fmaf(v, lng[col], lnb[col]));
        }
    }
    __syncthreads();

    /* phase 3: FMA from registers */
    float acc[4][4];
    #pragma unroll
    for (int b = 0; b < 4; b++)
        #pragma unroll
        for (int j = 0; j < 4; j++) acc[b][j] = 0.f;

    #pragma unroll
    for (int k = 0; k < KS; k++) {
        float4 w = wbuf[k];
        #pragma unroll
        for (int b = 0; b < 4; b++) {
            float a = As[b * KCH + k0 + k];
            acc[b][0] = fmaf(a, w.x, acc[b][0]);
            acc[b][1] = fmaf(a, w.y, acc[b][1]);
            acc[b][2] = fmaf(a, w.z, acc[b][2]);
            acc[b][3] = fmaf(a, w.w, acc[b][3]);
        }
    }
    #pragma unroll
    for (int b = 0; b < 4; b++)
        #pragma unroll
        for (int j = 0; j < 4; j++)
            red[s * 128 + g * 16 + b * 4 + j] = acc[b][j];
    __syncthreads();

    if (tid < 128) {
        float sum = 0.f;
        #pragma unroll
        for (int r = 0; r < 32; r++) sum += red[r * 128 + tid];
        int gg = tid >> 4, b = (tid >> 2) & 3, j = tid & 3;
        int col = blockIdx.x * 32 + gg * 4 + j;
        part_out[blockIdx.y * (BB * HID) + b * HID + col] = sum;
    }
}

/* ---------------- fused partial-reduce + bias + LayerNorm + gelu (standalone) ----- */
__global__ void __launch_bounds__(256) k_ln_gelu_p(
    const float* __restrict__ part, const float* __restrict__ bias,
    const float* __restrict__ g, const float* __restrict__ be,
    float* __restrict__ outv)
{
    int b = blockIdx.x, tid = threadIdx.x;
    float v[4];
    #pragma unroll
    for (int j = 0; j < 4; j++) {
        int col = tid + j * 256;
        float s = bias[col];
        #pragma unroll
        for (int kc = 0; kc < KSPLIT; kc++)
            s += part[kc * (BB * HID) + b * HID + col];
        v[j] = s;
    }
    float s1 = v[0] + v[1] + v[2] + v[3];
    float s2 = v[0]*v[0] + v[1]*v[1] + v[2]*v[2] + v[3]*v[3];
    #pragma unroll
    for (int o = 16; o; o >>= 1) {
        s1 += __shfl_xor_sync(0xffffffffu, s1, o);
        s2 += __shfl_xor_sync(0xffffffffu, s2, o);
    }
    __shared__ float rs[8], rs2[8], mv[2];
    int w = tid >> 5;
    if ((tid & 31) == 0) { rs[w] = s1; rs2[w] = s2; }
    __syncthreads();
    if (tid == 0) {
        float S = 0.f, S2 = 0.f;
        #pragma unroll
        for (int r = 0; r < 8; r++) { S += rs[r]; S2 += rs2[r]; }
        float mu  = S * (1.0f / HID);
        float var = S2 * (1.0f / HID) - mu * mu;
        mv[0] = mu; mv[1] = rsqrtf(var + 1e-5f);
    }
    __syncthreads();
    float mu = mv[0], rr = mv[1];
    float* o = outv + b * HID;
    #pragma unroll
    for (int j = 0; j < 4; j++) {
        int col = tid + j * 256;
        o[col] = geluf(fmaf((v[j] - mu) * rr, g[col], be[col]));
    }
}

/* ---------------- big GEMM pass 1: split-K x8 partials ---------------------------- */
__global__ void __launch_bounds__(128) k_gemm_big(
    const float* __restrict__ h2, const float* __restrict__ W,
    float* __restrict__ part)
{
    __shared__ float hsp[BB * 128];
    int tid = threadIdx.x;
    int kc  = blockIdx.y;
    int kbase = kc * (HID / KSPLIT);           /* 128 ks per chunk */
    #pragma unroll
    for (int i = 0; i < 4; i++) {
        int idx = tid + i * 128;
        hsp[idx] = h2[(idx >> 7) * HID + kbase + (idx & 127)];
    }
    __syncthreads();
    int col = blockIdx.x * 128 + tid;
    if (col >= MLPO) return;
    const float* w = W + (size_t)kbase * MLPO + col;
    float a0 = 0.f, a1 = 0.f, a2 = 0.f, a3 = 0.f;
    #pragma unroll 16
    for (int k = 0; k < 128; k++) {
        float wv = __ldg(w + (size_t)k * MLPO);
        a0 = fmaf(hsp[k],       wv, a0);
        a1 = fmaf(hsp[128 + k], wv, a1);
        a2 = fmaf(hsp[256 + k], wv, a2);
        a3 = fmaf(hsp[384 + k], wv, a3);
    }
    float* p = part + (size_t)kc * (BB * MLPP) + col;
    p[0]        = a0;
    p[MLPP]     = a1;
    p[2 * MLPP] = a2;
    p[3 * MLPP] = a3;
}

/* ---------------- big GEMM pass 2: float4 reduce over padded domain --------------- */
__global__ void __launch_bounds__(256) k_big_reduce(
    const float* __restrict__ part, const float* __restrict__ bias,
    float* __restrict__ outv)
{
    int idx = blockIdx.x * 256 + threadIdx.x;
    if (idx >= BB * (MLPP / 4)) return;
    int b = idx / (MLPP / 4), v = idx - b * (MLPP / 4);
    const float4* p = reinterpret_cast<const float4*>(part + (size_t)b * MLPP) + v;
    float4 s = {0.f, 0.f, 0.f, 0.f};
    #pragma unroll
    for (int kc = 0; kc < KSPLIT; kc++) {
        float4 t = p[(size_t)kc * (BB * MLPP / 4)];
        s.x += t.x; s.y += t.y; s.z += t.z; s.w += t.w;
    }
    int col = v * 4;
    s.x += (col     < MLPO) ? bias[col]     : 0.f;
    s.y += (col + 1 < MLPO) ? bias[col + 1] : 0.f;
    s.z += (col + 2 < MLPO) ? bias[col + 2] : 0.f;
    s.w += (col + 3 < MLPO) ? bias[col + 3] : 0.f;
    reinterpret_cast<float4*>(outv + (size_t)b * MLPP)[v] = s;
}

/* ---------------- ripple network evaluation ---------------------------------------
   Grid (37, 4): 148 blocks. 448 threads = 14 warps x 8 positions = 112 pos/block.
   Middle layers use plain __sinf (args ~<300, MUFU internal reduction suffices);
   this keeps the fma pipe below the MUFU floor -> pure MUFU-bound. */
__global__ void __launch_bounds__(448, 1) k_ripple(
    const float* __restrict__ mlp,
    const float* __restrict__ lcw, const float* __restrict__ lcb,
    const float* __restrict__ bypw, const float* __restrict__ bypb,
    float* __restrict__ outv)
{
    extern __shared__ float sm[];
    float2* wpS   = reinterpret_cast<float2*>(sm);          /* [2][64*65] float2 */
    float*  bwS   = sm + 16640;                              /* [2][64*66]        */
    float*  biasS = sm + 25088;                              /* [2][64]           */
    float2* woS   = reinterpret_cast<float2*>(sm + 25216);   /* [64]              */
    float*  bowS  = sm + 25344;                              /* [64]              */
    float*  lwS   = sm + 25408;
    float*  lbS   = sm + 25472;
    float*  scal  = sm + 25536;                              /* [8]               */
    float*  xsA   = sm + 25544;                              /* [14][512]         */

    int b   = blockIdx.y;
    int tid = threadIdx.x;
    const float* mo = mlp + b * MLPP;

    #pragma unroll
    for (int L = 0; L < 2; L++) {
        const float* base = mo + L * MIDD;
        const float2* wsrc = reinterpret_cast<const float2*>(base);
        for (int p = tid; p < 4096; p += 448) {
            float2 v = wsrc[p];
            wpS[L * 4160 + (p & 63) * 65 + (p >> 6)] = v;
        }
        const float* bsrc = base + 8192;
        for (int k = tid; k < 4160; k += 448) {
            float v = bsrc[k];
            int o = k / 65, j = k - o * 65;
            if (j == 0) biasS[L * 64 + o] = v;
            else        bwS[L * 4224 + (j - 1) * 66 + o] = v;
        }
    }
    if (tid < 64) {
        const float* ob = mo + 2 * MIDD;
        woS[tid]  = reinterpret_cast<const float2*>(ob)[tid];
        bowS[tid] = ob[129 + tid];
        lwS[tid]  = lcw[tid];
        lbS[tid]  = lcb[tid];
    }
    if (tid == 0) {
        scal[0] = mo[2 * MIDD + 128];
        scal[1] = bypw[0];
        scal[2] = bypw[1];
        scal[3] = bypb[0];
        scal[4] = bypb[1];
    }
    __syncthreads();

    int warp = tid >> 5, lane = tid & 31;
    int pos0 = blockIdx.x * 112 + warp * 8;
    if (pos0 >= SEQL) return;
    float* xs = xsA + warp * 512;

    for (int k = lane; k < 512; k += 32) {
        int q = k >> 6, i = k & 63;
        xs[k] = fmaf((float)(pos0 + q), lwS[i], lbS[i]);
    }
    __syncwarp();

    float byp;
    {
        float w0v = scal[1], w1v = scal[2];
        const float* xq = xs + (lane >> 2) * 64;
        int i0 = lane & 3;
        float a = 0.f;
        #pragma unroll
        for (int r = 0; r < 16; r++)
            a += sin_cw(fmaf(w0v, xq[i0 + 4 * r], w1v));
        byp = a * scal[4];
    }

    #pragma unroll
    for (int L = 0; L < 2; L++) {
        const float2* wp = wpS + L * 4160;
        const float*  bw = bwS + L * 4224;
        float accL[8], accH[8];
        #pragma unroll
        for (int q = 0; q < 8; q++) { accL[q] = 0.f; accH[q] = 0.f; }
        #pragma unroll 1
        for (int i = 0; i < 64; i++) {
            float2 wl = wp[i * 65 + lane];
            float2 wh = wp[i * 65 + 32 + lane];
            float  bl = bw[i * 66 + lane];
            float  bh = bw[i * 66 + 32 + lane];
            #pragma unroll
            for (int q = 0; q < 8; q++) {
                float xv = xs[q * 64 + i];
                float sl = __sinf(fmaf(wl.x, xv, wl.y));
                float sh = __sinf(fmaf(wh.x, xv, wh.y));
                accL[q] = fmaf(sl, bl, accL[q]);
                accH[q] = fmaf(sh, bh, accH[q]);
            }
        }
        __syncwarp();
        float cL = biasS[L * 64 + lane], cH = biasS[L * 64 + 32 + lane];
        #pragma unroll
        for (int q = 0; q < 8; q++) {
            xs[q * 64 + lane]      = geluf(accL[q] + cL);
            xs[q * 64 + 32 + lane] = geluf(accH[q] + cH);
        }
        __syncwarp();
    }

    float z = byp;
    {
        const float* xq = xs + (lane >> 2) * 64;
        int i0 = lane & 3;
        #pragma unroll
        for (int r = 0; r < 16; r++) {
            int i = i0 + 4 * r;
            float2 w = woS[i];
            z = fmaf(__sinf(fmaf(w.x, xq[i], w.y)), bowS[i], z);
        }
    }
    z += __shfl_xor_sync(0xffffffffu, z, 1);
    z += __shfl_xor_sync(0xffffffffu, z, 2);
    if ((lane & 3) == 0)
        outv[b * SEQL + pos0 + (lane >> 2)] = z + scal[0] + scal[3];
}

/* ---------------- launch ---------------- */
extern "C" void kernel_launch(void* const* d_in, const int* in_sizes, int n_in,
                              void* d_out, int out_size)
{
    (void)in_sizes; (void)n_in; (void)out_size;
    const float* x   = (const float*)d_in[0];
    const float* w0  = (const float*)d_in[1];
    const float* b0  = (const float*)d_in[2];
    const float* w1  = (const float*)d_in[3];
    const float* b1  = (const float*)d_in[4];
    const float* g1  = (const float*)d_in[5];
    const float* be1 = (const float*)d_in[6];
    const float* w2  = (const float*)d_in[7];
    const float* b2  = (const float*)d_in[8];
    const float* g2  = (const float*)d_in[9];
    const float* be2 = (const float*)d_in[10];
    const float* w3  = (const float*)d_in[11];
    const float* b3  = (const float*)d_in[12];
    const float* lcw = (const float*)d_in[13];
    const float* lcb = (const float*)d_in[14];
    const float* byw = (const float*)d_in[15];
    const float* byb = (const float*)d_in[16];
    float* out = (float*)d_out;

    float *h2, *pA, *pB, *mlp, *part;
    cudaGetSymbolAddress((void**)&h2,   g_h2);
    cudaGetSymbolAddress((void**)&pA,   g_pA);
    cudaGetSymbolAddress((void**)&pB,   g_pB);
    cudaGetSymbolAddress((void**)&mlp,  g_mlp);
    cudaGetSymbolAddress((void**)&part, g_part);

    /* h0 partials */
    k_gemm_sk<IN_DIM, 0><<<dim3(32, 8), 256>>>(x,  nullptr, nullptr, nullptr, w0, pA);
    /* z1 = gelu(reduce(pA)+b0) @ w1 -> pB */
    k_gemm_sk<HID,    1><<<dim3(32, 8), 256>>>(pA, b0, nullptr, nullptr, w1, pB);
    /* z2 = gelu(LN(reduce(pB)+b1)) @ w2 -> pA   (LN fused) */
    k_gemm_sk<HID,    2><<<dim3(32, 8), 256>>>(pB, b1, g1, be1, w2, pA);
    /* h2 = gelu(LN(reduce(pA)+b2)) */
    k_ln_gelu_p<<<4, 256>>>(pA, b2, g2, be2, h2);

    k_gemm_big<<<dim3((MLPO + 127) / 128, KSPLIT), 128>>>(h2, w3, part);
    k_big_reduce<<<(BB * (MLPP / 4) + 255) / 256, 256>>>(part, b3, mlp);

    const int rip_smem = (25544 + 14 * 512) * 4;   /* 130848 B */
    cudaFuncSetAttribute(k_ripple, cudaFuncAttributeMaxDynamicSharedMemorySize, rip_smem);
    k_ripple<<<dim3(37, 4), 448, rip_smem>>>(mlp, lcw, lcb, byw, byb, out);
}

// round 15
// speedup vs baseline: 2.7924x; 1.0354x over previous
#include <cuda_runtime.h>

#define BB     4
#define IN_DIM 512
#define HID    1024
#define SEQL   4096
#define RH     64
#define MIDD   12352      /* 2*64*64 + 65*64 */
#define MLPO   24897      /* 2*MIDD + 193 */
#define MLPP   24900      /* padded stride (16B-aligned rows) */
#define KSPLIT 8
#define GRID_HEAD 128

/* ---------------- scratch (no allocation allowed) ---------------- */
__device__ float g_h2[BB * HID];
__device__ __align__(16) float g_pA[KSPLIT * BB * HID];
__device__ __align__(16) float g_pB[KSPLIT * BB * HID];
__device__ __align__(16) float g_pC[KSPLIT * BB * HID];
__device__ __align__(16) float g_stat[8];
__device__ __align__(16) float g_mlp [BB * MLPP];
__device__ __align__(16) float g_part[KSPLIT * BB * MLPP];
__device__ unsigned g_bar[8];    /* zero-init; monotonic ticket counters */

/* ---------------- helpers ---------------- */
__device__ __forceinline__ float geluf(float x) {
    return 0.5f * x * (1.0f + erff(x * 0.70710678118654752440f));
}

/* 2-term Cody-Waite 2*pi reduction (bypass path: args up to ~4000). */
__device__ __forceinline__ float sin_cw(float x) {
    float n = rintf(x * 0.15915494309189535f);
    float r = fmaf(n, -6.2831854820251465f, x);
    r = fmaf(n, 1.7484556e-07f, r);
    return __sinf(r);
}

/* grid barrier: monotonic ticket counter, works across graph replays */
__device__ __forceinline__ void gbarrier(int id) {
    __syncthreads();
    if (threadIdx.x == 0) {
        __threadfence();                       /* release this block's writes */
        unsigned t = atomicAdd(&g_bar[id], 1u);
        unsigned tgt = (t / GRID_HEAD + 1u) * GRID_HEAD;
        volatile unsigned* p = &g_bar[id];
        while (*p < tgt) { }
        __threadfence();                       /* acquire others' writes */
    }
    __syncthreads();
}

/* ---------------- persistent head: 3 GEMMs + 2 LN, one kernel --------------------
   128 blocks x 256 thr, 1/SM (co-resident). Block (cb = bid>>3, kc = bid&7):
   64 cols x one K-chunk. 256 thr = 16 col-groups(4 cols, float4) x 16 K-slices.
   Weight prefetch for stage N+1 issued BEFORE stage-N barrier (latency hides
   under spin). Partials in distinct buffers pA/pB/pC (first-touch reads only
   -> no L1 staleness across barriers). */
__global__ void __launch_bounds__(256) k_head(
    const float* __restrict__ x,
    const float* __restrict__ w0, const float* __restrict__ b0,
    const float* __restrict__ w1, const float* __restrict__ b1,
    const float* __restrict__ g1, const float* __restrict__ be1,
    const float* __restrict__ w2, const float* __restrict__ b2,
    const float* __restrict__ g2, const float* __restrict__ be2,
    float* __restrict__ pA, float* __restrict__ pB, float* __restrict__ pC,
    float* __restrict__ stat, float* __restrict__ h2)
{
    __shared__ float As[BB * 128];
    __shared__ float red[16 * 256];
    __shared__ float rsA[8], rs2A[8], mvA[2];

    int tid = threadIdx.x, bid = blockIdx.x;
    int cb = bid >> 3, kc = bid & 7;
    int g = tid & 15, s = tid >> 4;
    int col0 = cb * 64 + g * 4;
    int gg = tid >> 4, ob = (tid >> 2) & 3, oj = tid & 3;
    int ocol = cb * 64 + gg * 4 + oj;

    /* ======== stage 1: h0-partials = x(4x512) @ w0 ======== */
    float4 wb1[8];                               /* w1 prefetch regs */
    {
        const int KCH = 64, KS = 4;
        int kbase = kc * KCH, k0 = s * KS;
        const float4* w4p = reinterpret_cast<const float4*>(w0 + col0);
        float4 wb[4];
        #pragma unroll
        for (int k = 0; k < 4; k++)
            wb[k] = __ldg(w4p + (size_t)(kbase + k0 + k) * (HID / 4));
        {   int i = tid;                          /* BB*KCH = 256 */
            int b = i >> 6, k = i & 63;
            As[b * KCH + k] = x[b * IN_DIM + kbase + k];
        }
        __syncthreads();
        float acc[4][4];
        #pragma unroll
        for (int b = 0; b < 4; b++) { acc[b][0]=0.f; acc[b][1]=0.f; acc[b][2]=0.f; acc[b][3]=0.f; }
        #pragma unroll
        for (int k = 0; k < KS; k++) {
            float4 w = wb[k];
            #pragma unroll
            for (int b = 0; b < 4; b++) {
                float a = As[b * KCH + k0 + k];
                acc[b][0] = fmaf(a, w.x, acc[b][0]);
                acc[b][1] = fmaf(a, w.y, acc[b][1]);
                acc[b][2] = fmaf(a, w.z, acc[b][2]);
                acc[b][3] = fmaf(a, w.w, acc[b][3]);
            }
        }
        #pragma unroll
        for (int b = 0; b < 4; b++)
            #pragma unroll
            for (int j = 0; j < 4; j++)
                red[s * 256 + g * 16 + b * 4 + j] = acc[b][j];
        __syncthreads();
        float sum = 0.f;
        #pragma unroll
        for (int r = 0; r < 16; r++) sum += red[r * 256 + tid];
        /* prefetch w1 for stage 2 (overlaps barrier) */
        {
            const float4* w4n = reinterpret_cast<const float4*>(w1 + col0);
            int kb2 = kc * 128, k02 = s * 8;
            #pragma unroll
            for (int k = 0; k < 8; k++)
                wb1[k] = __ldg(w4n + (size_t)(kb2 + k02 + k) * (HID / 4));
        }
        pA[kc * (BB * HID) + ob * HID + ocol] = sum;
    }
    gbarrier(0);

    /* ======== stage 2: z1-partials = gelu(reduce(pA)+b0) @ w1 ======== */
    float4 wb2[8];                               /* w2 prefetch regs */
    {
        const int KCH = 128, KS = 8;
        int kbase = kc * KCH, k0 = s * KS;
        #pragma unroll
        for (int ii = 0; ii < 2; ii++) {
            int i = tid + ii * 256;
            int b = i >> 7, k = i & 127;
            int col = kbase + k;
            float ss = b0[col];
            #pragma unroll
            for (int kk = 0; kk < KSPLIT; kk++)
                ss += pA[kk * (BB * HID) + b * HID + col];
            As[b * KCH + k] = geluf(ss);
        }
        __syncthreads();
        float acc[4][4];
        #pragma unroll
        for (int b = 0; b < 4; b++) { acc[b][0]=0.f; acc[b][1]=0.f; acc[b][2]=0.f; acc[b][3]=0.f; }
        #pragma unroll
        for (int k = 0; k < KS; k++) {
            float4 w = wb1[k];
            #pragma unroll
            for (int b = 0; b < 4; b++) {
                float a = As[b * KCH + k0 + k];
                acc[b][0] = fmaf(a, w.x, acc[b][0]);
                acc[b][1] = fmaf(a, w.y, acc[b][1]);
                acc[b][2] = fmaf(a, w.z, acc[b][2]);
                acc[b][3] = fmaf(a, w.w, acc[b][3]);
            }
        }
        #pragma unroll
        for (int b = 0; b < 4; b++)
            #pragma unroll
            for (int j = 0; j < 4; j++)
                red[s * 256 + g * 16 + b * 4 + j] = acc[b][j];
        __syncthreads();
        float sum = 0.f;
        #pragma unroll
        for (int r = 0; r < 16; r++) sum += red[r * 256 + tid];
        /* prefetch w2 for stage 3 (overlaps barrier + stats) */
        {
            const float4* w4n = reinterpret_cast<const float4*>(w2 + col0);
            int kb2 = kc * 128, k02 = s * 8;
            #pragma unroll
            for (int k = 0; k < 8; k++)
                wb2[k] = __ldg(w4n + (size_t)(kb2 + k02 + k) * (HID / 4));
        }
        pB[kc * (BB * HID) + ob * HID + ocol] = sum;
    }
    gbarrier(1);

    /* ======== LN1 stats (blocks 0..3, one per batch) ======== */
    if (bid < BB) {
        int b = bid;
        float vs[4];
        #pragma unroll
        for (int j = 0; j < 4; j++) {
            int col = tid + j * 256;
            float ss = b1[col];
            #pragma unroll
            for (int kk = 0; kk < KSPLIT; kk++)
                ss += pB[kk * (BB * HID) + b * HID + col];
            vs[j] = ss;
        }
        float s1 = vs[0]+vs[1]+vs[2]+vs[3];
        float s2 = vs[0]*vs[0]+vs[1]*vs[1]+vs[2]*vs[2]+vs[3]*vs[3];
        #pragma unroll
        for (int o = 16; o; o >>= 1) {
            s1 += __shfl_xor_sync(0xffffffffu, s1, o);
            s2 += __shfl_xor_sync(0xffffffffu, s2, o);
        }
        if ((tid & 31) == 0) { rsA[tid >> 5] = s1; rs2A[tid >> 5] = s2; }
        __syncthreads();
        if (tid == 0) {
            float S = 0.f, S2 = 0.f;
            #pragma unroll
            for (int r = 0; r < 8; r++) { S += rsA[r]; S2 += rs2A[r]; }
            float mu  = S * (1.0f / HID);
            float var = S2 * (1.0f / HID) - mu * mu;
            stat[b * 2]     = mu;
            stat[b * 2 + 1] = rsqrtf(var + 1e-5f);
        }
    }
    gbarrier(2);

    /* ======== stage 3: z2-partials = gelu(LN(reduce(pB)+b1)) @ w2 ======== */
    {
        const int KCH = 128, KS = 8;
        int kbase = kc * KCH, k0 = s * KS;
        #pragma unroll
        for (int ii = 0; ii < 2; ii++) {
            int i = tid + ii * 256;
            int b = i >> 7, k = i & 127;
            int col = kbase + k;
            float ss = b1[col];
            #pragma unroll
            for (int kk = 0; kk < KSPLIT; kk++)
                ss += pB[kk * (BB * HID) + b * HID + col];
            float v = (ss - stat[b * 2]) * stat[b * 2 + 1];
            As[b * KCH + k] = geluf(fmaf(v, g1[col], be1[col]));
        }
        __syncthreads();
        float acc[4][4];
        #pragma unroll
        for (int b = 0; b < 4; b++) { acc[b][0]=0.f; acc[b][1]=0.f; acc[b][2]=0.f; acc[b][3]=0.f; }
        #pragma unroll
        for (int k = 0; k < KS; k++) {
            float4 w = wb2[k];
            #pragma unroll
            for (int b = 0; b < 4; b++) {
                float a = As[b * KCH + k0 + k];
                acc[b][0] = fmaf(a, w.x, acc[b][0]);
                acc[b][1] = fmaf(a, w.y, acc[b][1]);
                acc[b][2] = fmaf(a, w.z, acc[b][2]);
                acc[b][3] = fmaf(a, w.w, acc[b][3]);
            }
        }
        #pragma unroll
        for (int b = 0; b < 4; b++)
            #pragma unroll
            for (int j = 0; j < 4; j++)
                red[s * 256 + g * 16 + b * 4 + j] = acc[b][j];
        __syncthreads();
        float sum = 0.f;
        #pragma unroll
        for (int r = 0; r < 16; r++) sum += red[r * 256 + tid];
        pC[kc * (BB * HID) + ob * HID + ocol] = sum;
    }
    gbarrier(3);

    /* ======== LN2 + gelu -> h2 (blocks 0..3) ======== */
    if (bid < BB) {
        int b = bid;
        float vs[4];
        #pragma unroll
        for (int j = 0; j < 4; j++) {
            int col = tid + j * 256;
            float ss = b2[col];
            #pragma unroll
            for (int kk = 0; kk < KSPLIT; kk++)
                ss += pC[kk * (BB * HID) + b * HID + col];
            vs[j] = ss;
        }
        float s1 = vs[0]+vs[1]+vs[2]+vs[3];
        float s2 = vs[0]*vs[0]+vs[1]*vs[1]+vs[2]*vs[2]+vs[3]*vs[3];
        #pragma unroll
        for (int o = 16; o; o >>= 1) {
            s1 += __shfl_xor_sync(0xffffffffu, s1, o);
            s2 += __shfl_xor_sync(0xffffffffu, s2, o);
        }
        if ((tid & 31) == 0) { rsA[tid >> 5] = s1; rs2A[tid >> 5] = s2; }
        __syncthreads();
        if (tid == 0) {
            float S = 0.f, S2 = 0.f;
            #pragma unroll
            for (int r = 0; r < 8; r++) { S += rsA[r]; S2 += rs2A[r]; }
            float mu  = S * (1.0f / HID);
            float var = S2 * (1.0f / HID) - mu * mu;
            mvA[0] = mu; mvA[1] = rsqrtf(var + 1e-5f);
        }
        __syncthreads();
        float mu = mvA[0], rr = mvA[1];
        #pragma unroll
        for (int j = 0; j < 4; j++) {
            int col = tid + j * 256;
            h2[b * HID + col] = geluf(fmaf((vs[j] - mu) * rr, g2[col], be2[col]));
        }
    }
}

/* ---------------- big GEMM pass 1: split-K x8 partials ---------------------------- */
__global__ void __launch_bounds__(128) k_gemm_big(
    const float* __restrict__ h2, const float* __restrict__ W,
    float* __restrict__ part)
{
    __shared__ float hsp[BB * 128];
    int tid = threadIdx.x;
    int kc  = blockIdx.y;
    int kbase = kc * (HID / KSPLIT);
    #pragma unroll
    for (int i = 0; i < 4; i++) {
        int idx = tid + i * 128;
        hsp[idx] = h2[(idx >> 7) * HID + kbase + (idx & 127)];
    }
    __syncthreads();
    int col = blockIdx.x * 128 + tid;
    if (col >= MLPO) return;
    const float* w = W + (size_t)kbase * MLPO + col;
    float a0 = 0.f, a1 = 0.f, a2 = 0.f, a3 = 0.f;
    #pragma unroll 16
    for (int k = 0; k < 128; k++) {
        float wv = __ldg(w + (size_t)k * MLPO);
        a0 = fmaf(hsp[k],       wv, a0);
        a1 = fmaf(hsp[128 + k], wv, a1);
        a2 = fmaf(hsp[256 + k], wv, a2);
        a3 = fmaf(hsp[384 + k], wv, a3);
    }
    float* p = part + (size_t)kc * (BB * MLPP) + col;
    p[0]        = a0;
    p[MLPP]     = a1;
    p[2 * MLPP] = a2;
    p[3 * MLPP] = a3;
}

/* ---------------- big GEMM pass 2: float4 reduce over padded domain --------------- */
__global__ void __launch_bounds__(256) k_big_reduce(
    const float* __restrict__ part, const float* __restrict__ bias,
    float* __restrict__ outv)
{
    int idx = blockIdx.x * 256 + threadIdx.x;
    if (idx >= BB * (MLPP / 4)) return;
    int b = idx / (MLPP / 4), v = idx - b * (MLPP / 4);
    const float4* p = reinterpret_cast<const float4*>(part + (size_t)b * MLPP) + v;
    float4 s = {0.f, 0.f, 0.f, 0.f};
    #pragma unroll
    for (int kc = 0; kc < KSPLIT; kc++) {
        float4 t = p[(size_t)kc * (BB * MLPP / 4)];
        s.x += t.x; s.y += t.y; s.z += t.z; s.w += t.w;
    }
    int col = v * 4;
    s.x += (col     < MLPO) ? bias[col]     : 0.f;
    s.y += (col + 1 < MLPO) ? bias[col + 1] : 0.f;
    s.z += (col + 2 < MLPO) ? bias[col + 2] : 0.f;
    s.w += (col + 3 < MLPO) ? bias[col + 3] : 0.f;
    reinterpret_cast<float4*>(outv + (size_t)b * MLPP)[v] = s;
}

/* ---------------- ripple network evaluation (MUFU-bound, ~32us floor) ------------- */
__global__ void __launch_bounds__(448, 1) k_ripple(
    const float* __restrict__ mlp,
    const float* __restrict__ lcw, const float* __restrict__ lcb,
    const float* __restrict__ bypw, const float* __restrict__ bypb,
    float* __restrict__ outv)
{
    extern __shared__ float sm[];
    float2* wpS   = reinterpret_cast<float2*>(sm);          /* [2][64*65] float2 */
    float*  bwS   = sm + 16640;                              /* [2][64*66]        */
    float*  biasS = sm + 25088;                              /* [2][64]           */
    float2* woS   = reinterpret_cast<float2*>(sm + 25216);   /* [64]              */
    float*  bowS  = sm + 25344;                              /* [64]              */
    float*  lwS   = sm + 25408;
    float*  lbS   = sm + 25472;
    float*  scal  = sm + 25536;                              /* [8]               */
    float*  xsA   = sm + 25544;                              /* [14][512]         */

    int b   = blockIdx.y;
    int tid = threadIdx.x;
    const float* mo = mlp + b * MLPP;

    #pragma unroll
    for (int L = 0; L < 2; L++) {
        const float* base = mo + L * MIDD;
        const float2* wsrc = reinterpret_cast<const float2*>(base);
        for (int p = tid; p < 4096; p += 448) {
            float2 v = wsrc[p];
            wpS[L * 4160 + (p & 63) * 65 + (p >> 6)] = v;
        }
        const float* bsrc = base + 8192;
        for (int k = tid; k < 4160; k += 448) {
            float v = bsrc[k];
            int o = k / 65, j = k - o * 65;
            if (j == 0) biasS[L * 64 + o] = v;
            else        bwS[L * 4224 + (j - 1) * 66 + o] = v;
        }
    }
    if (tid < 64) {
        const float* ob = mo + 2 * MIDD;
        woS[tid]  = reinterpret_cast<const float2*>(ob)[tid];
        bowS[tid] = ob[129 + tid];
        lwS[tid]  = lcw[tid];
        lbS[tid]  = lcb[tid];
    }
    if (tid == 0) {
        scal[0] = mo[2 * MIDD + 128];
        scal[1] = bypw[0];
        scal[2] = bypw[1];
        scal[3] = bypb[0];
        scal[4] = bypb[1];
    }
    __syncthreads();

    int warp = tid >> 5, lane = tid & 31;
    int pos0 = blockIdx.x * 112 + warp * 8;
    if (pos0 >= SEQL) return;
    float* xs = xsA + warp * 512;

    for (int k = lane; k < 512; k += 32) {
        int q = k >> 6, i = k & 63;
        xs[k] = fmaf((float)(pos0 + q), lwS[i], lbS[i]);
    }
    __syncwarp();

    float byp;
    {
        float w0v = scal[1], w1v = scal[2];
        const float* xq = xs + (lane >> 2) * 64;
        int i0 = lane & 3;
        float a = 0.f;
        #pragma unroll
        for (int r = 0; r < 16; r++)
            a += sin_cw(fmaf(w0v, xq[i0 + 4 * r], w1v));
        byp = a * scal[4];
    }

    #pragma unroll
    for (int L = 0; L < 2; L++) {
        const float2* wp = wpS + L * 4160;
        const float*  bw = bwS + L * 4224;
        float accL[8], accH[8];
        #pragma unroll
        for (int q = 0; q < 8; q++) { accL[q] = 0.f; accH[q] = 0.f; }
        #pragma unroll 1
        for (int i = 0; i < 64; i++) {
            float2 wl = wp[i * 65 + lane];
            float2 wh = wp[i * 65 + 32 + lane];
            float  bl = bw[i * 66 + lane];
            float  bh = bw[i * 66 + 32 + lane];
            #pragma unroll
            for (int q = 0; q < 8; q++) {
                float xv = xs[q * 64 + i];
                float sl = __sinf(fmaf(wl.x, xv, wl.y));
                float sh = __sinf(fmaf(wh.x, xv, wh.y));
                accL[q] = fmaf(sl, bl, accL[q]);
                accH[q] = fmaf(sh, bh, accH[q]);
            }
        }
        __syncwarp();
        float cL = biasS[L * 64 + lane], cH = biasS[L * 64 + 32 + lane];
        #pragma unroll
        for (int q = 0; q < 8; q++) {
            xs[q * 64 + lane]      = geluf(accL[q] + cL);
            xs[q * 64 + 32 + lane] = geluf(accH[q] + cH);
        }
        __syncwarp();
    }

    float z = byp;
    {
        const float* xq = xs + (lane >> 2) * 64;
        int i0 = lane & 3;
        #pragma unroll
        for (int r = 0; r < 16; r++) {
            int i = i0 + 4 * r;
            float2 w = woS[i];
            z = fmaf(__sinf(fmaf(w.x, xq[i], w.y)), bowS[i], z);
        }
    }
    z += __shfl_xor_sync(0xffffffffu, z, 1);
    z += __shfl_xor_sync(0xffffffffu, z, 2);
    if ((lane & 3) == 0)
        outv[b * SEQL + pos0 + (lane >> 2)] = z + scal[0] + scal[3];
}

/* ---------------- launch ---------------- */
extern "C" void kernel_launch(void* const* d_in, const int* in_sizes, int n_in,
                              void* d_out, int out_size)
{
    (void)in_sizes; (void)n_in; (void)out_size;
    const float* x   = (const float*)d_in[0];
    const float* w0  = (const float*)d_in[1];
    const float* b0  = (const float*)d_in[2];
    const float* w1  = (const float*)d_in[3];
    const float* b1  = (const float*)d_in[4];
    const float* g1  = (const float*)d_in[5];
    const float* be1 = (const float*)d_in[6];
    const float* w2  = (const float*)d_in[7];
    const float* b2  = (const float*)d_in[8];
    const float* g2  = (const float*)d_in[9];
    const float* be2 = (const float*)d_in[10];
    const float* w3  = (const float*)d_in[11];
    const float* b3  = (const float*)d_in[12];
    const float* lcw = (const float*)d_in[13];
    const float* lcb = (const float*)d_in[14];
    const float* byw = (const float*)d_in[15];
    const float* byb = (const float*)d_in[16];
    float* out = (float*)d_out;

    float *h2, *pA, *pB, *pC, *stat, *mlp, *part;
    cudaGetSymbolAddress((void**)&h2,   g_h2);
    cudaGetSymbolAddress((void**)&pA,   g_pA);
    cudaGetSymbolAddress((void**)&pB,   g_pB);
    cudaGetSymbolAddress((void**)&pC,   g_pC);
    cudaGetSymbolAddress((void**)&stat, g_stat);
    cudaGetSymbolAddress((void**)&mlp,  g_mlp);
    cudaGetSymbolAddress((void**)&part, g_part);

    k_head<<<GRID_HEAD, 256>>>(x, w0, b0, w1, b1, g1, be1,
                               w2, b2, g2, be2, pA, pB, pC, stat, h2);

    k_gemm_big<<<dim3((MLPO + 127) / 128, KSPLIT), 128>>>(h2, w3, part);
    k_big_reduce<<<(BB * (MLPP / 4) + 255) / 256, 256>>>(part, b3, mlp);

    const int rip_smem = (25544 + 14 * 512) * 4;   /* 130848 B */
    cudaFuncSetAttribute(k_ripple, cudaFuncAttributeMaxDynamicSharedMemorySize, rip_smem);
    k_ripple<<<dim3(37, 4), 448, rip_smem>>>(mlp, lcw, lcb, byw, byb, out);
}